// round 8
// baseline (speedup 1.0000x reference)
#include <cuda_runtime.h>
#include <math.h>
#include <stdint.h>

// ---------------- problem constants ----------------
namespace la {
constexpr int DIM    = 1024;
constexpr int NHEADS = 16;
constexpr int HD     = 64;
constexpr int NB     = 4;
constexpr int SEQ    = 4096;
constexpr int ROWS   = NB * SEQ; // 16384
constexpr int CHUNK  = 128;
constexpr int NCHUNK = SEQ / CHUNK; // 32
}

// ---------------- scratch (device globals: allocation-free) ----------------
__device__ float g_qkv[(size_t)la::ROWS * 3 * la::DIM];
__device__ float g_attn[(size_t)la::ROWS * la::DIM];
__device__ float g_ckv[(size_t)la::NB * la::NHEADS * la::NCHUNK * la::HD * la::HD];
__device__ float g_cks[(size_t)la::NB * la::NHEADS * la::NCHUNK * la::HD];
__device__ float g_wT[3072 * 1024 + 1024 * 1024];
__device__ float g_xr[(size_t)la::ROWS * la::DIM];   // tf32-rounded x
__device__ float2 g_lut[la::SEQ * 32];

// ---------------- helpers ----------------
__device__ __forceinline__ uint32_t cvt_tf32(float f) {
    uint32_t u;
    asm("cvt.rna.tf32.f32 %0, %1;" : "=r"(u) : "f"(f));
    return u;
}
__device__ __forceinline__ float tf32f(float f) { return __uint_as_float(cvt_tf32(f)); }

#define MMA_TF32(c, a, b0, b1)                                              \
    asm volatile("mma.sync.aligned.m16n8k8.row.col.f32.tf32.tf32.f32 "      \
                 "{%0,%1,%2,%3},{%4,%5,%6,%7},{%8,%9},{%0,%1,%2,%3};"       \
                 : "+f"((c)[0]), "+f"((c)[1]), "+f"((c)[2]), "+f"((c)[3])   \
                 : "r"((a)[0]), "r"((a)[1]), "r"((a)[2]), "r"((a)[3]),      \
                   "r"(b0), "r"(b1))

__device__ __forceinline__ float elu1(float z) {
    return (z > 0.f) ? (z + 1.0f) : expf(z);
}
constexpr float ROPE_SC = 0.35355339059327373f; // 64^(-1/4)

// ============ rope LUT build ==============================================
__global__ void rope_lut_build()
{
    const int n = blockIdx.x, lane = threadIdx.x;
    float pw   = powf(10000.0f, (float)lane * (1.0f / 32.0f));
    float invf = 1.0f / pw;
    float ang  = (float)n * invf;
    float s, c;
    sincosf(ang, &s, &c);
    g_lut[n * 32 + lane] = make_float2(c, s);
}

// ============ pre-round to tf32 ===========================================
__global__ __launch_bounds__(256) void round_tf32_k(const float* __restrict__ src,
                                                    float* __restrict__ dst)
{
    const size_t i = ((size_t)blockIdx.x * 256 + threadIdx.x) * 4;
    float4 v = *(const float4*)(src + i);
    uint4 u = { cvt_tf32(v.x), cvt_tf32(v.y), cvt_tf32(v.z), cvt_tf32(v.w) };
    *(uint4*)(dst + i) = u;
}

// ============ tf32 GEMM: C[M,N] = A[M,K] @ Bt[N,K]^T =====================
// CTA 128(M) x 256(N), 256 threads, 8 warps as 2(M) x 4(N), warp tile 64x64.
// BK=16, double-buffered LDG->reg->STS (round-4 pipeline), stride-20 smem.
// feat=1: fuse rope+elu+scale into the epilogue for q/k column blocks.
static constexpr int GB_STR   = 20;
static constexpr int GB_A     = 128 * GB_STR;         // floats
static constexpr int GB_B     = 256 * GB_STR;         // floats
static constexpr int GB_STAGE = GB_A + GB_B;          // 7680 floats
static constexpr int GB_SMEM  = 2 * GB_STAGE * 4;     // 61440 bytes

__global__ __launch_bounds__(256, 1) void gemm_big(const float* __restrict__ A,
                                                   const float* __restrict__ Bt,
                                                   float* __restrict__ C,
                                                   int M, int N, int K, int feat)
{
    extern __shared__ float smf[];
    float* sA[2] = { smf,            smf + GB_STAGE };
    float* sB[2] = { smf + GB_A,     smf + GB_STAGE + GB_A };

    const int tid  = threadIdx.x;
    const int wid  = tid >> 5, lane = tid & 31;
    const int g    = lane >> 2, tig = lane & 3;
    const int wm   = (wid & 1) * 64;        // M offset of warp tile
    const int wn   = (wid >> 1) * 64;       // N offset of warp tile

    const float* Ab = A  + (size_t)blockIdx.y * 128 * K;
    const float* Bb = Bt + (size_t)blockIdx.x * 256 * K;

    const int arow = tid >> 1, aq = (tid & 1) * 8;

    float4 ra[2], rb[4];
    auto ldg = [&](int k0) {
        const float* ga = Ab + (size_t)arow * K + k0 + aq;
        ra[0] = *(const float4*)(ga);
        ra[1] = *(const float4*)(ga + 4);
        const float* gb = Bb + (size_t)tid * K + k0;
#pragma unroll
        for (int j = 0; j < 4; j++) rb[j] = *(const float4*)(gb + j * 4);
    };
    auto sts = [&](int buf) {
        *(float4*)(sA[buf] + arow * GB_STR + aq)     = ra[0];
        *(float4*)(sA[buf] + arow * GB_STR + aq + 4) = ra[1];
#pragma unroll
        for (int j = 0; j < 4; j++)
            *(float4*)(sB[buf] + tid * GB_STR + j * 4) = rb[j];
    };

    float acc[4][8][4];
#pragma unroll
    for (int mt = 0; mt < 4; mt++)
#pragma unroll
        for (int nt = 0; nt < 8; nt++)
#pragma unroll
            for (int i = 0; i < 4; i++) acc[mt][nt][i] = 0.f;

    auto compute = [&](int buf) {
        const uint32_t* uA = (const uint32_t*)sA[buf];
        const uint32_t* uB = (const uint32_t*)sB[buf];
#pragma unroll
        for (int ks = 0; ks < 2; ks++) {
            const int kb = ks * 8;
            uint32_t af[4][4];
#pragma unroll
            for (int mt = 0; mt < 4; mt++) {
                int r = wm + mt * 16 + g;
                af[mt][0] = uA[r * GB_STR + kb + tig];
                af[mt][1] = uA[(r + 8) * GB_STR + kb + tig];
                af[mt][2] = uA[r * GB_STR + kb + tig + 4];
                af[mt][3] = uA[(r + 8) * GB_STR + kb + tig + 4];
            }
#pragma unroll
            for (int nt = 0; nt < 8; nt++) {
                int n = wn + nt * 8 + g;
                uint32_t b0 = uB[n * GB_STR + kb + tig];
                uint32_t b1 = uB[n * GB_STR + kb + tig + 4];
#pragma unroll
                for (int mt = 0; mt < 4; mt++)
                    MMA_TF32(acc[mt][nt], af[mt], b0, b1);
            }
        }
    };

    ldg(0);
    sts(0);
    __syncthreads();
    const int KT = K >> 4;
    for (int k = 0; k < KT; k++) {
        if (k + 1 < KT) ldg((k + 1) << 4);
        compute(k & 1);
        if (k + 1 < KT) sts((k + 1) & 1);
        __syncthreads();
    }

    // ---------------- epilogue ----------------
    const int colbase = blockIdx.x * 256 + wn;     // 64-aligned
    const int which   = colbase >> 10;             // 0=q 1=k 2=v (uniform per warp tile)
    const bool dofeat = feat && (which < 2);

    if (!dofeat) {
#pragma unroll
        for (int mt = 0; mt < 4; mt++) {
            const int r0 = blockIdx.y * 128 + wm + mt * 16 + g;
#pragma unroll
            for (int nt = 0; nt < 8; nt++) {
                const int col = colbase + nt * 8 + tig * 2;
                *(float2*)(C + (size_t)r0 * N + col) =
                    make_float2(acc[mt][nt][0], acc[mt][nt][1]);
                *(float2*)(C + (size_t)(r0 + 8) * N + col) =
                    make_float2(acc[mt][nt][2], acc[mt][nt][3]);
            }
        }
    } else {
        // rope + elu + scale: pair (d, d+32) = (acc[..][nt], acc[..][nt+4])
#pragma unroll
        for (int mt = 0; mt < 4; mt++) {
            const int r0 = blockIdx.y * 128 + wm + mt * 16 + g;
#pragma unroll
            for (int half = 0; half < 2; half++) {
                const int row = r0 + half * 8;
                const int n4  = row & (la::SEQ - 1);
#pragma unroll
                for (int nt = 0; nt < 4; nt++) {
#pragma unroll
                    for (int e = 0; e < 2; e++) {
                        const int d  = nt * 8 + tig * 2 + e;
                        const int ai = half * 2 + e;
                        float x1 = acc[mt][nt][ai];
                        float x2 = acc[mt][nt + 4][ai];
                        float2 cs = g_lut[n4 * 32 + d];
                        float o1 = (x1 * cs.x - x2 * cs.y) * ROPE_SC;
                        float o2 = (x1 * cs.y + x2 * cs.x) * ROPE_SC;
                        C[(size_t)row * N + colbase + d]      = tf32f(elu1(o1));
                        C[(size_t)row * N + colbase + d + 32] = tf32f(elu1(o2));
                    }
                }
            }
        }
    }
}

// ---------------- weight transpose (rounds to tf32 at store) ---------------
__global__ __launch_bounds__(256) void transpose_w(const float* __restrict__ src,
                                                   float* __restrict__ dst,
                                                   int R, int Ccols)
{
    __shared__ float t[32][33];
    const int bx = blockIdx.x * 32, by = blockIdx.y * 32;
    const int x = threadIdx.x & 31, y = threadIdx.x >> 5;
#pragma unroll
    for (int i = 0; i < 32; i += 8)
        t[y + i][x] = src[(size_t)(by + y + i) * Ccols + bx + x];
    __syncthreads();
#pragma unroll
    for (int i = 0; i < 32; i += 8)
        dst[(size_t)(bx + y + i) * R + by + x] = tf32f(t[x][y + i]);
}

// ============ chunk_sums: KV_c = K^T @ V (mma), ks = colsum(K) ============
// q/k in g_qkv are ALREADY featurized (gemm1 epilogue). Plain staging.
static constexpr int CS_SMEM = 16896 * 4;

__global__ __launch_bounds__(256) void chunk_sums()
{
    extern __shared__ float sm[];
    float* sKT = sm;          // [d][t]
    float* sVT = sm + 8448;   // [m][t]

    const int c  = blockIdx.x;
    const int bh = blockIdx.y;
    const int b  = bh >> 4, h = bh & 15;
    const int tid = threadIdx.x;
    const int wid = tid >> 5, lane = tid & 31;
    const int g = lane >> 2, tig = lane & 3;

    const size_t rowbase = (size_t)(b * la::SEQ + c * la::CHUNK) * 3072 + h * 64;
    const float* kg = g_qkv + rowbase + 1024;
    const float* vg = g_qkv + rowbase + 2048;

#pragma unroll
    for (int i = 0; i < 8; i++) {
        int idx = i * 256 + tid;
        int t = idx >> 4, m0 = (idx & 15) << 2;
        float4 k4 = *(const float4*)(kg + (size_t)t * 3072 + m0);
        sKT[(m0 + 0) * 132 + t] = k4.x;
        sKT[(m0 + 1) * 132 + t] = k4.y;
        sKT[(m0 + 2) * 132 + t] = k4.z;
        sKT[(m0 + 3) * 132 + t] = k4.w;
        float4 v4 = *(const float4*)(vg + (size_t)t * 3072 + m0);
        sVT[(m0 + 0) * 132 + t] = tf32f(v4.x);
        sVT[(m0 + 1) * 132 + t] = tf32f(v4.y);
        sVT[(m0 + 2) * 132 + t] = tf32f(v4.z);
        sVT[(m0 + 3) * 132 + t] = tf32f(v4.w);
    }
    __syncthreads();

    const int wm = (wid & 3) * 16, wn = (wid >> 2) * 32;
    const uint32_t* uK = (const uint32_t*)sKT;
    const uint32_t* uV = (const uint32_t*)sVT;
    float acc[4][4];
#pragma unroll
    for (int nt = 0; nt < 4; nt++)
#pragma unroll
        for (int i = 0; i < 4; i++) acc[nt][i] = 0.f;

#pragma unroll
    for (int ks = 0; ks < 16; ks++) {
        const int kb = ks * 8;
        uint32_t af[4];
        af[0] = uK[(wm + g) * 132 + kb + tig];
        af[1] = uK[(wm + g + 8) * 132 + kb + tig];
        af[2] = uK[(wm + g) * 132 + kb + tig + 4];
        af[3] = uK[(wm + g + 8) * 132 + kb + tig + 4];
#pragma unroll
        for (int nt = 0; nt < 4; nt++) {
            int n = wn + nt * 8 + g;
            uint32_t b0 = uV[n * 132 + kb + tig];
            uint32_t b1 = uV[n * 132 + kb + tig + 4];
            MMA_TF32(acc[nt], af, b0, b1);
        }
    }
    float* outp = g_ckv + ((size_t)bh * la::NCHUNK + c) * 4096;
#pragma unroll
    for (int nt = 0; nt < 4; nt++) {
        int d = wm + g, m = wn + nt * 8 + tig * 2;
        *(float2*)(outp + d * 64 + m)       = make_float2(acc[nt][0], acc[nt][1]);
        *(float2*)(outp + (d + 8) * 64 + m) = make_float2(acc[nt][2], acc[nt][3]);
    }
    if (tid < 64) {
        float s = 0.f;
        for (int t = 0; t < 128; t++) s += sKT[tid * 132 + t];
        g_cks[((size_t)bh * la::NCHUNK + c) * 64 + tid] = s;
    }
}

// ---------------- exclusive prefix over chunks -----------------------------
__global__ __launch_bounds__(256) void prefix_scan()
{
    const int bh  = blockIdx.x;
    const int seg = blockIdx.y;
    const int tid = threadIdx.x;

    float2* base = (float2*)(g_ckv + (size_t)bh * la::NCHUNK * 4096) + seg * 256 + tid;
    float2 vals[la::NCHUNK];
#pragma unroll
    for (int c = 0; c < la::NCHUNK; c++) vals[c] = base[c * 2048];
    float2 run = make_float2(0.f, 0.f);
#pragma unroll
    for (int c = 0; c < la::NCHUNK; c++) {
        float2 t = vals[c];
        vals[c] = run;
        run.x += t.x; run.y += t.y;
    }
#pragma unroll
    for (int c = 0; c < la::NCHUNK; c++) base[c * 2048] = vals[c];

    if (seg == 0 && tid < 64) {
        float* kb = g_cks + (size_t)bh * la::NCHUNK * 64 + tid;
        float kv[la::NCHUNK];
#pragma unroll
        for (int c = 0; c < la::NCHUNK; c++) kv[c] = kb[c * 64];
        float r = 0.f;
#pragma unroll
        for (int c = 0; c < la::NCHUNK; c++) { float t = kv[c]; kv[c] = r; r += t; }
#pragma unroll
        for (int c = 0; c < la::NCHUNK; c++) kb[c * 64] = kv[c];
    }
}

// ============ chunk_out: mma-based intra + inter ==========================
static constexpr int CO_SMEM = 38848 * 4;

__global__ __launch_bounds__(256) void chunk_out()
{
    extern __shared__ float sm[];
    float* sQ   = sm;             // [r][d]  (68 stride)
    float* sK   = sm + 8704;      // [t][d]  (later sVT)
    float* sVT  = sm + 8704;      // [m][t]  (132 stride)
    float* sS   = sm + 17408;     // [r][j]  (132 stride)
    float* sKVT = sm + 34304;     // [m][d]  (68 stride)
    float* sks  = sm + 38656;
    float* sden = sm + 38720;

    const int c  = blockIdx.x;
    const int bh = blockIdx.y;
    const int b  = bh >> 4, h = bh & 15;
    const int tid = threadIdx.x;
    const int wid = tid >> 5, lane = tid & 31;
    const int g = lane >> 2, tig = lane & 3;

    const size_t rowbase = (size_t)(b * la::SEQ + c * la::CHUNK) * 3072 + h * 64;
    const float* qg = g_qkv + rowbase;
    const float* kg = qg + 1024;
    const float* vg = qg + 2048;

    // plain staging: q,k already featurized+tf32
#pragma unroll
    for (int i = 0; i < 8; i++) {
        int idx = i * 256 + tid;
        int t = idx >> 4, d0 = (idx & 15) << 2;
        *(float4*)(sQ + t * 68 + d0) = *(const float4*)(qg + (size_t)t * 3072 + d0);
        *(float4*)(sK + t * 68 + d0) = *(const float4*)(kg + (size_t)t * 3072 + d0);
    }
    const float* kvg = g_ckv + ((size_t)bh * la::NCHUNK + c) * 4096;
#pragma unroll
    for (int i = 0; i < 4; i++) {
        int idx = i * 256 + tid;
        int d = idx >> 4, m0 = (idx & 15) << 2;
        float4 kv4 = *(const float4*)(kvg + d * 64 + m0);
        sKVT[(m0 + 0) * 68 + d] = tf32f(kv4.x);
        sKVT[(m0 + 1) * 68 + d] = tf32f(kv4.y);
        sKVT[(m0 + 2) * 68 + d] = tf32f(kv4.z);
        sKVT[(m0 + 3) * 68 + d] = tf32f(kv4.w);
    }
    if (tid < 64) sks[tid] = g_cks[((size_t)bh * la::NCHUNK + c) * 64 + tid];
    __syncthreads();

    // stage1: S = Qf @ Kf^T
    {
        const int wm = (wid & 3) * 32, wn = (wid >> 2) * 64;
        const uint32_t* uA = (const uint32_t*)sQ;
        const uint32_t* uB = (const uint32_t*)sK;
        float acc[2][8][4];
#pragma unroll
        for (int mt = 0; mt < 2; mt++)
#pragma unroll
            for (int nt = 0; nt < 8; nt++)
#pragma unroll
                for (int i = 0; i < 4; i++) acc[mt][nt][i] = 0.f;
#pragma unroll
        for (int ks = 0; ks < 8; ks++) {
            const int kb = ks * 8;
            uint32_t af[2][4];
#pragma unroll
            for (int mt = 0; mt < 2; mt++) {
                int r = wm + mt * 16 + g;
                af[mt][0] = uA[r * 68 + kb + tig];
                af[mt][1] = uA[(r + 8) * 68 + kb + tig];
                af[mt][2] = uA[r * 68 + kb + tig + 4];
                af[mt][3] = uA[(r + 8) * 68 + kb + tig + 4];
            }
#pragma unroll
            for (int nt = 0; nt < 8; nt++) {
                int n = wn + nt * 8 + g;
                uint32_t b0 = uB[n * 68 + kb + tig];
                uint32_t b1 = uB[n * 68 + kb + tig + 4];
                MMA_TF32(acc[0][nt], af[0], b0, b1);
                MMA_TF32(acc[1][nt], af[1], b0, b1);
            }
        }
        __syncthreads();

#pragma unroll
        for (int mt = 0; mt < 2; mt++) {
            int r0 = wm + mt * 16 + g, r1 = r0 + 8;
#pragma unroll
            for (int nt = 0; nt < 8; nt++) {
                int j0 = wn + nt * 8 + tig * 2;
                float v00 = (j0     <= r0) ? tf32f(acc[mt][nt][0]) : 0.f;
                float v01 = (j0 + 1 <= r0) ? tf32f(acc[mt][nt][1]) : 0.f;
                float v10 = (j0     <= r1) ? tf32f(acc[mt][nt][2]) : 0.f;
                float v11 = (j0 + 1 <= r1) ? tf32f(acc[mt][nt][3]) : 0.f;
                *(float2*)(sS + r0 * 132 + j0) = make_float2(v00, v01);
                *(float2*)(sS + r1 * 132 + j0) = make_float2(v10, v11);
            }
        }
    }
#pragma unroll
    for (int i = 0; i < 8; i++) {
        int idx = i * 256 + tid;
        int t = idx >> 4, m0 = (idx & 15) << 2;
        float4 v4 = *(const float4*)(vg + (size_t)t * 3072 + m0);
        sVT[(m0 + 0) * 132 + t] = tf32f(v4.x);
        sVT[(m0 + 1) * 132 + t] = tf32f(v4.y);
        sVT[(m0 + 2) * 132 + t] = tf32f(v4.z);
        sVT[(m0 + 3) * 132 + t] = tf32f(v4.w);
    }
    __syncthreads();

    if (tid < 128) {
        const int r = tid;
        float s = 0.f;
        for (int j = 0; j < 128; j++) s += sS[r * 132 + j];
        for (int d = 0; d < 64; d++) s = fmaf(sQ[r * 68 + d], sks[d], s);
        sden[r] = fmaxf(s, 1e-6f);
    }
    __syncthreads();

    // stage2: out = S_masked @ V + Qf @ KV^T
    {
        const int wm = (wid & 3) * 32, wn = (wid >> 2) * 32;
        const uint32_t* uS = (const uint32_t*)sS;
        const uint32_t* uV = (const uint32_t*)sVT;
        const uint32_t* uQ = (const uint32_t*)sQ;
        const uint32_t* uKV = (const uint32_t*)sKVT;
        float acc[2][4][4];
#pragma unroll
        for (int mt = 0; mt < 2; mt++)
#pragma unroll
            for (int nt = 0; nt < 4; nt++)
#pragma unroll
                for (int i = 0; i < 4; i++) acc[mt][nt][i] = 0.f;

#pragma unroll
        for (int ks = 0; ks < 16; ks++) {
            const int kb = ks * 8;
            uint32_t af[2][4];
#pragma unroll
            for (int mt = 0; mt < 2; mt++) {
                int r = wm + mt * 16 + g;
                af[mt][0] = uS[r * 132 + kb + tig];
                af[mt][1] = uS[(r + 8) * 132 + kb + tig];
                af[mt][2] = uS[r * 132 + kb + tig + 4];
                af[mt][3] = uS[(r + 8) * 132 + kb + tig + 4];
            }
#pragma unroll
            for (int nt = 0; nt < 4; nt++) {
                int n = wn + nt * 8 + g;
                uint32_t b0 = uV[n * 132 + kb + tig];
                uint32_t b1 = uV[n * 132 + kb + tig + 4];
                MMA_TF32(acc[0][nt], af[0], b0, b1);
                MMA_TF32(acc[1][nt], af[1], b0, b1);
            }
        }
#pragma unroll
        for (int ks = 0; ks < 8; ks++) {
            const int kb = ks * 8;
            uint32_t af[2][4];
#pragma unroll
            for (int mt = 0; mt < 2; mt++) {
                int r = wm + mt * 16 + g;
                af[mt][0] = uQ[r * 68 + kb + tig];
                af[mt][1] = uQ[(r + 8) * 68 + kb + tig];
                af[mt][2] = uQ[r * 68 + kb + tig + 4];
                af[mt][3] = uQ[(r + 8) * 68 + kb + tig + 4];
            }
#pragma unroll
            for (int nt = 0; nt < 4; nt++) {
                int n = wn + nt * 8 + g;
                uint32_t b0 = uKV[n * 68 + kb + tig];
                uint32_t b1 = uKV[n * 68 + kb + tig + 4];
                MMA_TF32(acc[0][nt], af[0], b0, b1);
                MMA_TF32(acc[1][nt], af[1], b0, b1);
            }
        }

        // epilogue: divide, round to tf32 (feeds the pre-rounded GEMM)
#pragma unroll
        for (int mt = 0; mt < 2; mt++) {
            int r0 = wm + mt * 16 + g, r1 = r0 + 8;
            float inv0 = 1.0f / sden[r0];
            float inv1 = 1.0f / sden[r1];
            float* o0 = g_attn + (size_t)(b * la::SEQ + c * la::CHUNK + r0) * 1024 + h * 64;
            float* o1 = g_attn + (size_t)(b * la::SEQ + c * la::CHUNK + r1) * 1024 + h * 64;
#pragma unroll
            for (int nt = 0; nt < 4; nt++) {
                int m = wn + nt * 8 + tig * 2;
                *(float2*)(o0 + m) = make_float2(tf32f(acc[mt][nt][0] * inv0),
                                                 tf32f(acc[mt][nt][1] * inv0));
                *(float2*)(o1 + m) = make_float2(tf32f(acc[mt][nt][2] * inv1),
                                                 tf32f(acc[mt][nt][3] * inv1));
            }
        }
    }
}

// ---------------- launch ----------------
extern "C" void kernel_launch(void* const* d_in, const int* in_sizes, int n_in,
                              void* d_out, int out_size)
{
    const float* x    = (const float*)d_in[0];
    const float* wqkv = (const float*)d_in[1];
    const float* wout = (const float*)d_in[2];
    float*       out  = (float*)d_out;

    float *qkv, *attn, *wT, *xr;
    cudaGetSymbolAddress((void**)&qkv, g_qkv);
    cudaGetSymbolAddress((void**)&attn, g_attn);
    cudaGetSymbolAddress((void**)&wT, g_wT);
    cudaGetSymbolAddress((void**)&xr, g_xr);
    float* wqkvT = wT;
    float* woutT = wT + 3072 * 1024;

    cudaFuncSetAttribute(gemm_big,   cudaFuncAttributeMaxDynamicSharedMemorySize, GB_SMEM);
    cudaFuncSetAttribute(chunk_sums, cudaFuncAttributeMaxDynamicSharedMemorySize, CS_SMEM);
    cudaFuncSetAttribute(chunk_out,  cudaFuncAttributeMaxDynamicSharedMemorySize, CO_SMEM);

    // 0) rope LUT, tf32-rounded weight transposes, tf32-rounded x
    rope_lut_build<<<la::SEQ, 32>>>();
    transpose_w<<<dim3(3072 / 32, 1024 / 32), 256>>>(wqkv, wqkvT, 1024, 3072);
    transpose_w<<<dim3(1024 / 32, 1024 / 32), 256>>>(wout, woutT, 1024, 1024);
    round_tf32_k<<<la::ROWS * la::DIM / 1024, 256>>>(x, xr);

    // 1) qkv = x @ w_qkv, with rope+elu fused into the q/k epilogue
    gemm_big<<<dim3(3072 / 256, la::ROWS / 128), 256, GB_SMEM>>>(xr, wqkvT, qkv,
                                                                 la::ROWS, 3072, 1024, 1);

    // 2) per-chunk KV sums
    dim3 g3(la::NCHUNK, la::NB * la::NHEADS);
    chunk_sums<<<g3, 256, CS_SMEM>>>();

    // 3) exclusive prefix over chunks
    prefix_scan<<<dim3(la::NB * la::NHEADS, 8), 256>>>();

    // 4) per-chunk outputs
    chunk_out<<<g3, 256, CO_SMEM>>>();

    // 5) out = attn @ w_out
    gemm_big<<<dim3(1024 / 256, la::ROWS / 128), 256, GB_SMEM>>>(attn, woutT, out,
                                                                 la::ROWS, 1024, 1024, 0);
}

// round 9
// speedup vs baseline: 1.5428x; 1.5428x over previous
#include <cuda_runtime.h>
#include <math.h>
#include <stdint.h>

// ---------------- problem constants ----------------
namespace la {
constexpr int DIM    = 1024;
constexpr int NHEADS = 16;
constexpr int HD     = 64;
constexpr int NB     = 4;
constexpr int SEQ    = 4096;
constexpr int ROWS   = NB * SEQ; // 16384
constexpr int CHUNK  = 128;
constexpr int NCHUNK = SEQ / CHUNK; // 32
}

// ---------------- scratch (device globals: allocation-free) ----------------
__device__ float g_qkv[(size_t)la::ROWS * 3 * la::DIM];
__device__ float g_attn[(size_t)la::ROWS * la::DIM];
__device__ float g_ckv[(size_t)la::NB * la::NHEADS * la::NCHUNK * la::HD * la::HD];
__device__ float g_cks[(size_t)la::NB * la::NHEADS * la::NCHUNK * la::HD];
__device__ float g_wT[3072 * 1024 + 1024 * 1024];
__device__ float g_xr[(size_t)la::ROWS * la::DIM];   // tf32-rounded x
__device__ float2 g_lut[la::SEQ * 32];

// ---------------- helpers ----------------
__device__ __forceinline__ uint32_t cvt_tf32(float f) {
    uint32_t u;
    asm("cvt.rna.tf32.f32 %0, %1;" : "=r"(u) : "f"(f));
    return u;
}
__device__ __forceinline__ float tf32f(float f) { return __uint_as_float(cvt_tf32(f)); }

#define MMA_TF32(c, a, b0, b1)                                              \
    asm volatile("mma.sync.aligned.m16n8k8.row.col.f32.tf32.tf32.f32 "      \
                 "{%0,%1,%2,%3},{%4,%5,%6,%7},{%8,%9},{%0,%1,%2,%3};"       \
                 : "+f"((c)[0]), "+f"((c)[1]), "+f"((c)[2]), "+f"((c)[3])   \
                 : "r"((a)[0]), "r"((a)[1]), "r"((a)[2]), "r"((a)[3]),      \
                   "r"(b0), "r"(b1))

__device__ __forceinline__ float elu1(float z) {
    return (z > 0.f) ? (z + 1.0f) : expf(z);
}
constexpr float ROPE_SC = 0.35355339059327373f; // 64^(-1/4)

// ============ rope LUT build ==============================================
__global__ void rope_lut_build()
{
    const int n = blockIdx.x, lane = threadIdx.x;
    float pw   = powf(10000.0f, (float)lane * (1.0f / 32.0f));
    float invf = 1.0f / pw;
    float ang  = (float)n * invf;
    float s, c;
    sincosf(ang, &s, &c);
    g_lut[n * 32 + lane] = make_float2(c, s);
}

// ============ pre-round to tf32 ===========================================
__global__ __launch_bounds__(256) void round_tf32_k(const float* __restrict__ src,
                                                    float* __restrict__ dst)
{
    const size_t i = ((size_t)blockIdx.x * 256 + threadIdx.x) * 4;
    float4 v = *(const float4*)(src + i);
    uint4 u = { cvt_tf32(v.x), cvt_tf32(v.y), cvt_tf32(v.z), cvt_tf32(v.w) };
    *(uint4*)(dst + i) = u;
}

// ============ tf32 GEMM (round-4 geometry): C = A[M,K] @ Bt[N,K]^T ========
// 128x128 CTA tile, BK=32, 256 threads (8 warps), warp tile 32x64, occ 2.
// Inputs pre-rounded to tf32 -> no cvt in hot loop.
// feat=1: rope+elu+scale fused into the epilogue for q/k column blocks.
static constexpr int GM_STRIDE = 36;
static constexpr int GM_TILE   = 128 * GM_STRIDE;
static constexpr int GM_SMEM   = 4 * GM_TILE * 4; // 73728 B

__global__ __launch_bounds__(256, 2) void gemm_mma(const float* __restrict__ A,
                                                   const float* __restrict__ Bt,
                                                   float* __restrict__ C,
                                                   int M, int N, int K, int feat)
{
    extern __shared__ float smf[];
    float* sA[2] = { smf,           smf + 2 * GM_TILE };
    float* sB[2] = { smf + GM_TILE, smf + 3 * GM_TILE };

    const int tid  = threadIdx.x;
    const int wid  = tid >> 5, lane = tid & 31;
    const int g    = lane >> 2, tig = lane & 3;
    const int wm   = (wid & 3) * 32, wn = (wid >> 2) * 64;

    const float* Ab = A  + (size_t)blockIdx.y * 128 * K;
    const float* Bb = Bt + (size_t)blockIdx.x * 128 * K;

    float acc[2][8][4];
#pragma unroll
    for (int mt = 0; mt < 2; mt++)
#pragma unroll
        for (int nt = 0; nt < 8; nt++)
#pragma unroll
            for (int i = 0; i < 4; i++) acc[mt][nt][i] = 0.f;

    float4 ra[4], rb[4];
    auto ldg = [&](int kc) {
#pragma unroll
        for (int i = 0; i < 4; i++) {
            int lin = i * 256 + tid;
            int r = lin >> 3, q = (lin & 7) << 2;
            ra[i] = *(const float4*)(Ab + (size_t)r * K + kc * 32 + q);
            rb[i] = *(const float4*)(Bb + (size_t)r * K + kc * 32 + q);
        }
    };
    auto sts = [&](int buf) {
#pragma unroll
        for (int i = 0; i < 4; i++) {
            int lin = i * 256 + tid;
            int r = lin >> 3, q = (lin & 7) << 2;
            *(float4*)(sA[buf] + r * GM_STRIDE + q) = ra[i];
            *(float4*)(sB[buf] + r * GM_STRIDE + q) = rb[i];
        }
    };
    auto compute = [&](int buf) {
        const uint32_t* uA = (const uint32_t*)sA[buf];
        const uint32_t* uB = (const uint32_t*)sB[buf];
#pragma unroll
        for (int ks = 0; ks < 4; ks++) {
            const int kb = ks * 8;
            uint32_t af[2][4];
#pragma unroll
            for (int mt = 0; mt < 2; mt++) {
                int r = wm + mt * 16 + g;
                af[mt][0] = uA[r * GM_STRIDE + kb + tig];
                af[mt][1] = uA[(r + 8) * GM_STRIDE + kb + tig];
                af[mt][2] = uA[r * GM_STRIDE + kb + tig + 4];
                af[mt][3] = uA[(r + 8) * GM_STRIDE + kb + tig + 4];
            }
#pragma unroll
            for (int nt = 0; nt < 8; nt++) {
                int n = wn + nt * 8 + g;
                uint32_t b0 = uB[n * GM_STRIDE + kb + tig];
                uint32_t b1 = uB[n * GM_STRIDE + kb + tig + 4];
                MMA_TF32(acc[0][nt], af[0], b0, b1);
                MMA_TF32(acc[1][nt], af[1], b0, b1);
            }
        }
    };

    ldg(0);
    sts(0);
    __syncthreads();
    const int KC = K >> 5;
    for (int kc = 0; kc < KC; kc++) {
        const int cur = kc & 1;
        if (kc + 1 < KC) ldg(kc + 1);
        compute(cur);
        if (kc + 1 < KC) sts(cur ^ 1);
        __syncthreads();
    }

    // ---------------- epilogue ----------------
    const int colbase = blockIdx.x * 128 + wn;   // 64-aligned
    const int which   = colbase >> 10;           // 0=q 1=k 2=v
    const bool dofeat = feat && (which < 2);

    if (!dofeat) {
#pragma unroll
        for (int mt = 0; mt < 2; mt++) {
            const int row0 = blockIdx.y * 128 + wm + mt * 16 + g;
#pragma unroll
            for (int nt = 0; nt < 8; nt++) {
                const int col = colbase + nt * 8 + tig * 2;
                *(float2*)(C + (size_t)row0 * N + col) =
                    make_float2(acc[mt][nt][0], acc[mt][nt][1]);
                *(float2*)(C + (size_t)(row0 + 8) * N + col) =
                    make_float2(acc[mt][nt][2], acc[mt][nt][3]);
            }
        }
    } else {
        // rope + elu + scale: pair (d, d+32) = (acc[..][nt], acc[..][nt+4])
#pragma unroll
        for (int mt = 0; mt < 2; mt++) {
            const int r0 = blockIdx.y * 128 + wm + mt * 16 + g;
#pragma unroll
            for (int half = 0; half < 2; half++) {
                const int row = r0 + half * 8;
                const int n4  = row & (la::SEQ - 1);
#pragma unroll
                for (int nt = 0; nt < 4; nt++) {
#pragma unroll
                    for (int e = 0; e < 2; e++) {
                        const int d  = nt * 8 + tig * 2 + e;
                        const int ai = half * 2 + e;
                        float x1 = acc[mt][nt][ai];
                        float x2 = acc[mt][nt + 4][ai];
                        float2 cs = g_lut[n4 * 32 + d];
                        float o1 = (x1 * cs.x - x2 * cs.y) * ROPE_SC;
                        float o2 = (x1 * cs.y + x2 * cs.x) * ROPE_SC;
                        C[(size_t)row * N + colbase + d]      = tf32f(elu1(o1));
                        C[(size_t)row * N + colbase + d + 32] = tf32f(elu1(o2));
                    }
                }
            }
        }
    }
}

// ---------------- weight transpose (rounds to tf32 at store) ---------------
__global__ __launch_bounds__(256) void transpose_w(const float* __restrict__ src,
                                                   float* __restrict__ dst,
                                                   int R, int Ccols)
{
    __shared__ float t[32][33];
    const int bx = blockIdx.x * 32, by = blockIdx.y * 32;
    const int x = threadIdx.x & 31, y = threadIdx.x >> 5;
#pragma unroll
    for (int i = 0; i < 32; i += 8)
        t[y + i][x] = src[(size_t)(by + y + i) * Ccols + bx + x];
    __syncthreads();
#pragma unroll
    for (int i = 0; i < 32; i += 8)
        dst[(size_t)(bx + y + i) * R + by + x] = tf32f(t[x][y + i]);
}

// ============ chunk_sums: KV_c = K^T @ V (mma), ks = colsum(K) ============
// q/k in g_qkv are ALREADY featurized+tf32 (gemm1 epilogue). Plain staging.
static constexpr int CS_SMEM = 16896 * 4;

__global__ __launch_bounds__(256) void chunk_sums()
{
    extern __shared__ float sm[];
    float* sKT = sm;          // [d][t]
    float* sVT = sm + 8448;   // [m][t]

    const int c  = blockIdx.x;
    const int bh = blockIdx.y;
    const int b  = bh >> 4, h = bh & 15;
    const int tid = threadIdx.x;
    const int wid = tid >> 5, lane = tid & 31;
    const int g = lane >> 2, tig = lane & 3;

    const size_t rowbase = (size_t)(b * la::SEQ + c * la::CHUNK) * 3072 + h * 64;
    const float* kg = g_qkv + rowbase + 1024;
    const float* vg = g_qkv + rowbase + 2048;

#pragma unroll
    for (int i = 0; i < 8; i++) {
        int idx = i * 256 + tid;
        int t = idx >> 4, m0 = (idx & 15) << 2;
        float4 k4 = *(const float4*)(kg + (size_t)t * 3072 + m0);
        sKT[(m0 + 0) * 132 + t] = k4.x;
        sKT[(m0 + 1) * 132 + t] = k4.y;
        sKT[(m0 + 2) * 132 + t] = k4.z;
        sKT[(m0 + 3) * 132 + t] = k4.w;
        float4 v4 = *(const float4*)(vg + (size_t)t * 3072 + m0);
        sVT[(m0 + 0) * 132 + t] = tf32f(v4.x);
        sVT[(m0 + 1) * 132 + t] = tf32f(v4.y);
        sVT[(m0 + 2) * 132 + t] = tf32f(v4.z);
        sVT[(m0 + 3) * 132 + t] = tf32f(v4.w);
    }
    __syncthreads();

    const int wm = (wid & 3) * 16, wn = (wid >> 2) * 32;
    const uint32_t* uK = (const uint32_t*)sKT;
    const uint32_t* uV = (const uint32_t*)sVT;
    float acc[4][4];
#pragma unroll
    for (int nt = 0; nt < 4; nt++)
#pragma unroll
        for (int i = 0; i < 4; i++) acc[nt][i] = 0.f;

#pragma unroll
    for (int ks = 0; ks < 16; ks++) {
        const int kb = ks * 8;
        uint32_t af[4];
        af[0] = uK[(wm + g) * 132 + kb + tig];
        af[1] = uK[(wm + g + 8) * 132 + kb + tig];
        af[2] = uK[(wm + g) * 132 + kb + tig + 4];
        af[3] = uK[(wm + g + 8) * 132 + kb + tig + 4];
#pragma unroll
        for (int nt = 0; nt < 4; nt++) {
            int n = wn + nt * 8 + g;
            uint32_t b0 = uV[n * 132 + kb + tig];
            uint32_t b1 = uV[n * 132 + kb + tig + 4];
            MMA_TF32(acc[nt], af, b0, b1);
        }
    }
    float* outp = g_ckv + ((size_t)bh * la::NCHUNK + c) * 4096;
#pragma unroll
    for (int nt = 0; nt < 4; nt++) {
        int d = wm + g, m = wn + nt * 8 + tig * 2;
        *(float2*)(outp + d * 64 + m)       = make_float2(acc[nt][0], acc[nt][1]);
        *(float2*)(outp + (d + 8) * 64 + m) = make_float2(acc[nt][2], acc[nt][3]);
    }
    if (tid < 64) {
        float s = 0.f;
        for (int t = 0; t < 128; t++) s += sKT[tid * 132 + t];
        g_cks[((size_t)bh * la::NCHUNK + c) * 64 + tid] = s;
    }
}

// ---------------- exclusive prefix over chunks -----------------------------
__global__ __launch_bounds__(256) void prefix_scan()
{
    const int bh  = blockIdx.x;
    const int seg = blockIdx.y;
    const int tid = threadIdx.x;

    float2* base = (float2*)(g_ckv + (size_t)bh * la::NCHUNK * 4096) + seg * 256 + tid;
    float2 vals[la::NCHUNK];
#pragma unroll
    for (int c = 0; c < la::NCHUNK; c++) vals[c] = base[c * 2048];
    float2 run = make_float2(0.f, 0.f);
#pragma unroll
    for (int c = 0; c < la::NCHUNK; c++) {
        float2 t = vals[c];
        vals[c] = run;
        run.x += t.x; run.y += t.y;
    }
#pragma unroll
    for (int c = 0; c < la::NCHUNK; c++) base[c * 2048] = vals[c];

    if (seg == 0 && tid < 64) {
        float* kb = g_cks + (size_t)bh * la::NCHUNK * 64 + tid;
        float kv[la::NCHUNK];
#pragma unroll
        for (int c = 0; c < la::NCHUNK; c++) kv[c] = kb[c * 64];
        float r = 0.f;
#pragma unroll
        for (int c = 0; c < la::NCHUNK; c++) { float t = kv[c]; kv[c] = r; r += t; }
#pragma unroll
        for (int c = 0; c < la::NCHUNK; c++) kb[c * 64] = kv[c];
    }
}

// ============ chunk_out: mma-based intra + inter ==========================
static constexpr int CO_SMEM = 38848 * 4;

__global__ __launch_bounds__(256) void chunk_out()
{
    extern __shared__ float sm[];
    float* sQ   = sm;             // [r][d]  (68 stride)
    float* sK   = sm + 8704;      // [t][d]  (later sVT)
    float* sVT  = sm + 8704;      // [m][t]  (132 stride)
    float* sS   = sm + 17408;     // [r][j]  (132 stride)
    float* sKVT = sm + 34304;     // [m][d]  (68 stride)
    float* sks  = sm + 38656;
    float* sden = sm + 38720;

    const int c  = blockIdx.x;
    const int bh = blockIdx.y;
    const int b  = bh >> 4, h = bh & 15;
    const int tid = threadIdx.x;
    const int wid = tid >> 5, lane = tid & 31;
    const int g = lane >> 2, tig = lane & 3;

    const size_t rowbase = (size_t)(b * la::SEQ + c * la::CHUNK) * 3072 + h * 64;
    const float* qg = g_qkv + rowbase;
    const float* kg = qg + 1024;
    const float* vg = qg + 2048;

    // plain staging: q,k already featurized+tf32
#pragma unroll
    for (int i = 0; i < 8; i++) {
        int idx = i * 256 + tid;
        int t = idx >> 4, d0 = (idx & 15) << 2;
        *(float4*)(sQ + t * 68 + d0) = *(const float4*)(qg + (size_t)t * 3072 + d0);
        *(float4*)(sK + t * 68 + d0) = *(const float4*)(kg + (size_t)t * 3072 + d0);
    }
    const float* kvg = g_ckv + ((size_t)bh * la::NCHUNK + c) * 4096;
#pragma unroll
    for (int i = 0; i < 4; i++) {
        int idx = i * 256 + tid;
        int d = idx >> 4, m0 = (idx & 15) << 2;
        float4 kv4 = *(const float4*)(kvg + d * 64 + m0);
        sKVT[(m0 + 0) * 68 + d] = tf32f(kv4.x);
        sKVT[(m0 + 1) * 68 + d] = tf32f(kv4.y);
        sKVT[(m0 + 2) * 68 + d] = tf32f(kv4.z);
        sKVT[(m0 + 3) * 68 + d] = tf32f(kv4.w);
    }
    if (tid < 64) sks[tid] = g_cks[((size_t)bh * la::NCHUNK + c) * 64 + tid];
    __syncthreads();

    // stage1: S = Qf @ Kf^T
    {
        const int wm = (wid & 3) * 32, wn = (wid >> 2) * 64;
        const uint32_t* uA = (const uint32_t*)sQ;
        const uint32_t* uB = (const uint32_t*)sK;
        float acc[2][8][4];
#pragma unroll
        for (int mt = 0; mt < 2; mt++)
#pragma unroll
            for (int nt = 0; nt < 8; nt++)
#pragma unroll
                for (int i = 0; i < 4; i++) acc[mt][nt][i] = 0.f;
#pragma unroll
        for (int ks = 0; ks < 8; ks++) {
            const int kb = ks * 8;
            uint32_t af[2][4];
#pragma unroll
            for (int mt = 0; mt < 2; mt++) {
                int r = wm + mt * 16 + g;
                af[mt][0] = uA[r * 68 + kb + tig];
                af[mt][1] = uA[(r + 8) * 68 + kb + tig];
                af[mt][2] = uA[r * 68 + kb + tig + 4];
                af[mt][3] = uA[(r + 8) * 68 + kb + tig + 4];
            }
#pragma unroll
            for (int nt = 0; nt < 8; nt++) {
                int n = wn + nt * 8 + g;
                uint32_t b0 = uB[n * 68 + kb + tig];
                uint32_t b1 = uB[n * 68 + kb + tig + 4];
                MMA_TF32(acc[0][nt], af[0], b0, b1);
                MMA_TF32(acc[1][nt], af[1], b0, b1);
            }
        }
        __syncthreads();

#pragma unroll
        for (int mt = 0; mt < 2; mt++) {
            int r0 = wm + mt * 16 + g, r1 = r0 + 8;
#pragma unroll
            for (int nt = 0; nt < 8; nt++) {
                int j0 = wn + nt * 8 + tig * 2;
                float v00 = (j0     <= r0) ? tf32f(acc[mt][nt][0]) : 0.f;
                float v01 = (j0 + 1 <= r0) ? tf32f(acc[mt][nt][1]) : 0.f;
                float v10 = (j0     <= r1) ? tf32f(acc[mt][nt][2]) : 0.f;
                float v11 = (j0 + 1 <= r1) ? tf32f(acc[mt][nt][3]) : 0.f;
                *(float2*)(sS + r0 * 132 + j0) = make_float2(v00, v01);
                *(float2*)(sS + r1 * 132 + j0) = make_float2(v10, v11);
            }
        }
    }
#pragma unroll
    for (int i = 0; i < 8; i++) {
        int idx = i * 256 + tid;
        int t = idx >> 4, m0 = (idx & 15) << 2;
        float4 v4 = *(const float4*)(vg + (size_t)t * 3072 + m0);
        sVT[(m0 + 0) * 132 + t] = tf32f(v4.x);
        sVT[(m0 + 1) * 132 + t] = tf32f(v4.y);
        sVT[(m0 + 2) * 132 + t] = tf32f(v4.z);
        sVT[(m0 + 3) * 132 + t] = tf32f(v4.w);
    }
    __syncthreads();

    if (tid < 128) {
        const int r = tid;
        float s = 0.f;
        for (int j = 0; j < 128; j++) s += sS[r * 132 + j];
        for (int d = 0; d < 64; d++) s = fmaf(sQ[r * 68 + d], sks[d], s);
        sden[r] = fmaxf(s, 1e-6f);
    }
    __syncthreads();

    // stage2: out = S_masked @ V + Qf @ KV^T
    {
        const int wm = (wid & 3) * 32, wn = (wid >> 2) * 32;
        const uint32_t* uS = (const uint32_t*)sS;
        const uint32_t* uV = (const uint32_t*)sVT;
        const uint32_t* uQ = (const uint32_t*)sQ;
        const uint32_t* uKV = (const uint32_t*)sKVT;
        float acc[2][4][4];
#pragma unroll
        for (int mt = 0; mt < 2; mt++)
#pragma unroll
            for (int nt = 0; nt < 4; nt++)
#pragma unroll
                for (int i = 0; i < 4; i++) acc[mt][nt][i] = 0.f;

#pragma unroll
        for (int ks = 0; ks < 16; ks++) {
            const int kb = ks * 8;
            uint32_t af[2][4];
#pragma unroll
            for (int mt = 0; mt < 2; mt++) {
                int r = wm + mt * 16 + g;
                af[mt][0] = uS[r * 132 + kb + tig];
                af[mt][1] = uS[(r + 8) * 132 + kb + tig];
                af[mt][2] = uS[r * 132 + kb + tig + 4];
                af[mt][3] = uS[(r + 8) * 132 + kb + tig + 4];
            }
#pragma unroll
            for (int nt = 0; nt < 4; nt++) {
                int n = wn + nt * 8 + g;
                uint32_t b0 = uV[n * 132 + kb + tig];
                uint32_t b1 = uV[n * 132 + kb + tig + 4];
                MMA_TF32(acc[0][nt], af[0], b0, b1);
                MMA_TF32(acc[1][nt], af[1], b0, b1);
            }
        }
#pragma unroll
        for (int ks = 0; ks < 8; ks++) {
            const int kb = ks * 8;
            uint32_t af[2][4];
#pragma unroll
            for (int mt = 0; mt < 2; mt++) {
                int r = wm + mt * 16 + g;
                af[mt][0] = uQ[r * 68 + kb + tig];
                af[mt][1] = uQ[(r + 8) * 68 + kb + tig];
                af[mt][2] = uQ[r * 68 + kb + tig + 4];
                af[mt][3] = uQ[(r + 8) * 68 + kb + tig + 4];
            }
#pragma unroll
            for (int nt = 0; nt < 4; nt++) {
                int n = wn + nt * 8 + g;
                uint32_t b0 = uKV[n * 68 + kb + tig];
                uint32_t b1 = uKV[n * 68 + kb + tig + 4];
                MMA_TF32(acc[0][nt], af[0], b0, b1);
                MMA_TF32(acc[1][nt], af[1], b0, b1);
            }
        }

        // epilogue: divide, round to tf32 (feeds the pre-rounded GEMM)
#pragma unroll
        for (int mt = 0; mt < 2; mt++) {
            int r0 = wm + mt * 16 + g, r1 = r0 + 8;
            float inv0 = 1.0f / sden[r0];
            float inv1 = 1.0f / sden[r1];
            float* o0 = g_attn + (size_t)(b * la::SEQ + c * la::CHUNK + r0) * 1024 + h * 64;
            float* o1 = g_attn + (size_t)(b * la::SEQ + c * la::CHUNK + r1) * 1024 + h * 64;
#pragma unroll
            for (int nt = 0; nt < 4; nt++) {
                int m = wn + nt * 8 + tig * 2;
                *(float2*)(o0 + m) = make_float2(tf32f(acc[mt][nt][0] * inv0),
                                                 tf32f(acc[mt][nt][1] * inv0));
                *(float2*)(o1 + m) = make_float2(tf32f(acc[mt][nt][2] * inv1),
                                                 tf32f(acc[mt][nt][3] * inv1));
            }
        }
    }
}

// ---------------- launch ----------------
extern "C" void kernel_launch(void* const* d_in, const int* in_sizes, int n_in,
                              void* d_out, int out_size)
{
    const float* x    = (const float*)d_in[0];
    const float* wqkv = (const float*)d_in[1];
    const float* wout = (const float*)d_in[2];
    float*       out  = (float*)d_out;

    float *qkv, *attn, *wT, *xr;
    cudaGetSymbolAddress((void**)&qkv, g_qkv);
    cudaGetSymbolAddress((void**)&attn, g_attn);
    cudaGetSymbolAddress((void**)&wT, g_wT);
    cudaGetSymbolAddress((void**)&xr, g_xr);
    float* wqkvT = wT;
    float* woutT = wT + 3072 * 1024;

    cudaFuncSetAttribute(gemm_mma,   cudaFuncAttributeMaxDynamicSharedMemorySize, GM_SMEM);
    cudaFuncSetAttribute(chunk_sums, cudaFuncAttributeMaxDynamicSharedMemorySize, CS_SMEM);
    cudaFuncSetAttribute(chunk_out,  cudaFuncAttributeMaxDynamicSharedMemorySize, CO_SMEM);

    // 0) rope LUT, tf32-rounded weight transposes, tf32-rounded x
    rope_lut_build<<<la::SEQ, 32>>>();
    transpose_w<<<dim3(3072 / 32, 1024 / 32), 256>>>(wqkv, wqkvT, 1024, 3072);
    transpose_w<<<dim3(1024 / 32, 1024 / 32), 256>>>(wout, woutT, 1024, 1024);
    round_tf32_k<<<la::ROWS * la::DIM / 1024, 256>>>(x, xr);

    // 1) qkv = x @ w_qkv, rope+elu fused into q/k epilogue
    gemm_mma<<<dim3(3072 / 128, la::ROWS / 128), 256, GM_SMEM>>>(xr, wqkvT, qkv,
                                                                 la::ROWS, 3072, 1024, 1);

    // 2) per-chunk KV sums
    dim3 g3(la::NCHUNK, la::NB * la::NHEADS);
    chunk_sums<<<g3, 256, CS_SMEM>>>();

    // 3) exclusive prefix over chunks
    prefix_scan<<<dim3(la::NB * la::NHEADS, 8), 256>>>();

    // 4) per-chunk outputs
    chunk_out<<<g3, 256, CO_SMEM>>>();

    // 5) out = attn @ w_out
    gemm_mma<<<dim3(1024 / 128, la::ROWS / 128), 256, GM_SMEM>>>(attn, woutT, out,
                                                                 la::ROWS, 1024, 1024, 0);
}

// round 10
// speedup vs baseline: 1.9081x; 1.2367x over previous
#include <cuda_runtime.h>
#include <math.h>
#include <stdint.h>

// ---------------- problem constants ----------------
namespace la {
constexpr int DIM    = 1024;
constexpr int NHEADS = 16;
constexpr int HD     = 64;
constexpr int NB     = 4;
constexpr int SEQ    = 4096;
constexpr int ROWS   = NB * SEQ; // 16384
constexpr int CHUNK  = 128;
constexpr int NCHUNK = SEQ / CHUNK; // 32
}

// ---------------- scratch (device globals: allocation-free) ----------------
__device__ float g_qkv[(size_t)la::ROWS * 3 * la::DIM];
__device__ float g_attn[(size_t)la::ROWS * la::DIM];
__device__ float g_ckv[(size_t)la::NB * la::NHEADS * la::NCHUNK * la::HD * la::HD];
__device__ float g_cks[(size_t)la::NB * la::NHEADS * la::NCHUNK * la::HD];
__device__ float g_wT[3072 * 1024 + 1024 * 1024];
__device__ float g_xr[(size_t)la::ROWS * la::DIM];   // tf32-rounded x
__device__ float2 g_lut[la::SEQ * 32];

// ---------------- helpers ----------------
__device__ __forceinline__ uint32_t cvt_tf32(float f) {
    uint32_t u;
    asm("cvt.rna.tf32.f32 %0, %1;" : "=r"(u) : "f"(f));
    return u;
}
__device__ __forceinline__ float tf32f(float f) { return __uint_as_float(cvt_tf32(f)); }

__device__ __forceinline__ uint32_t smem_u32(const void* p) {
    uint32_t a;
    asm("{ .reg .u64 t; cvta.to.shared.u64 t, %1; cvt.u32.u64 %0, t; }" : "=r"(a) : "l"(p));
    return a;
}

#define MMA_TF32(c, a, b0, b1)                                              \
    asm volatile("mma.sync.aligned.m16n8k8.row.col.f32.tf32.tf32.f32 "      \
                 "{%0,%1,%2,%3},{%4,%5,%6,%7},{%8,%9},{%0,%1,%2,%3};"       \
                 : "+f"((c)[0]), "+f"((c)[1]), "+f"((c)[2]), "+f"((c)[3])   \
                 : "r"((a)[0]), "r"((a)[1]), "r"((a)[2]), "r"((a)[3]),      \
                   "r"(b0), "r"(b1))

#define CP_ASYNC16(dst, src) \
    asm volatile("cp.async.cg.shared.global [%0], [%1], 16;" :: "r"(dst), "l"(src) : "memory")
#define CP_COMMIT  asm volatile("cp.async.commit_group;" ::: "memory")
#define CP_WAIT1   asm volatile("cp.async.wait_group 1;" ::: "memory")

__device__ __forceinline__ float elu1(float z) {
    return (z > 0.f) ? (z + 1.0f) : expf(z);
}
constexpr float ROPE_SC = 0.35355339059327373f; // 64^(-1/4)

// ============ rope LUT build ==============================================
__global__ void rope_lut_build()
{
    const int n = blockIdx.x, lane = threadIdx.x;
    float pw   = powf(10000.0f, (float)lane * (1.0f / 32.0f));
    float invf = 1.0f / pw;
    float ang  = (float)n * invf;
    float s, c;
    sincosf(ang, &s, &c);
    g_lut[n * 32 + lane] = make_float2(c, s);
}

// ============ pre-round to tf32 ===========================================
__global__ __launch_bounds__(256) void round_tf32_k(const float* __restrict__ src,
                                                    float* __restrict__ dst)
{
    const size_t i = ((size_t)blockIdx.x * 256 + threadIdx.x) * 4;
    float4 v = *(const float4*)(src + i);
    uint4 u = { cvt_tf32(v.x), cvt_tf32(v.y), cvt_tf32(v.z), cvt_tf32(v.w) };
    *(uint4*)(dst + i) = u;
}

// ============ tf32 GEMM (R4 geometry + cp.async 3-stage) ==================
// C = A[M,K] @ Bt[N,K]^T. 128x128 CTA tile, BK=32, 256 threads (8 warps),
// warp tile 32x64, occ 2 (16 warps/SM). Inputs pre-rounded to tf32.
// feat=1: rope+elu+scale fused into the epilogue for q/k column blocks.
static constexpr int GM_STRIDE = 36;
static constexpr int GM_HALF   = 128 * GM_STRIDE;     // A tile floats
static constexpr int GM_STAGE  = 2 * GM_HALF;         // 9216 floats
static constexpr int GM_SMEM   = 3 * GM_STAGE * 4;    // 110592 B

__global__ __launch_bounds__(256, 2) void gemm_mma(const float* __restrict__ A,
                                                   const float* __restrict__ Bt,
                                                   float* __restrict__ C,
                                                   int M, int N, int K, int feat)
{
    extern __shared__ float smf[];
    const uint32_t sbase = smem_u32(smf);

    const int tid  = threadIdx.x;
    const int wid  = tid >> 5, lane = tid & 31;
    const int g    = lane >> 2, tig = lane & 3;
    const int wm   = (wid & 3) * 32, wn = (wid >> 2) * 64;

    const float* Ab = A  + (size_t)blockIdx.y * 128 * K;
    const float* Bb = Bt + (size_t)blockIdx.x * 128 * K;

    const int lr = tid >> 3, lq = (tid & 7) << 2;   // per-i base row/col

    auto load_stage = [&](int s, int kc) {
        const uint32_t base = sbase + s * (GM_STAGE * 4);
#pragma unroll
        for (int i = 0; i < 4; i++) {
            const int r = lr + i * 32;              // lin = i*256+tid -> r = lin>>3
            const uint32_t off = (r * GM_STRIDE + lq) * 4;
            CP_ASYNC16(base + off,               Ab + (size_t)r * K + kc * 32 + lq);
            CP_ASYNC16(base + GM_HALF * 4 + off, Bb + (size_t)r * K + kc * 32 + lq);
        }
        CP_COMMIT;
    };

    float acc[2][8][4];
#pragma unroll
    for (int mt = 0; mt < 2; mt++)
#pragma unroll
        for (int nt = 0; nt < 8; nt++)
#pragma unroll
            for (int i = 0; i < 4; i++) acc[mt][nt][i] = 0.f;

    auto compute = [&](int buf) {
        const uint32_t* uA = (const uint32_t*)smf + buf * GM_STAGE;
        const uint32_t* uB = uA + GM_HALF;
#pragma unroll
        for (int ks = 0; ks < 4; ks++) {
            const int kb = ks * 8;
            uint32_t af[2][4];
#pragma unroll
            for (int mt = 0; mt < 2; mt++) {
                int r = wm + mt * 16 + g;
                af[mt][0] = uA[r * GM_STRIDE + kb + tig];
                af[mt][1] = uA[(r + 8) * GM_STRIDE + kb + tig];
                af[mt][2] = uA[r * GM_STRIDE + kb + tig + 4];
                af[mt][3] = uA[(r + 8) * GM_STRIDE + kb + tig + 4];
            }
#pragma unroll
            for (int nt = 0; nt < 8; nt++) {
                int n = wn + nt * 8 + g;
                uint32_t b0 = uB[n * GM_STRIDE + kb + tig];
                uint32_t b1 = uB[n * GM_STRIDE + kb + tig + 4];
                MMA_TF32(acc[0][nt], af[0], b0, b1);
                MMA_TF32(acc[1][nt], af[1], b0, b1);
            }
        }
    };

    load_stage(0, 0);
    load_stage(1, 1);

    const int KC = K >> 5;
    for (int kc = 0; kc < KC; kc++) {
        CP_WAIT1;
        __syncthreads();
        compute(kc % 3);
        if (kc + 2 < KC) load_stage((kc + 2) % 3, kc + 2);
        else             CP_COMMIT;   // keep group count consistent
    }

    // ---------------- epilogue ----------------
    const int colbase = blockIdx.x * 128 + wn;   // 64-aligned
    const int which   = colbase >> 10;           // 0=q 1=k 2=v
    const bool dofeat = feat && (which < 2);

    if (!dofeat) {
#pragma unroll
        for (int mt = 0; mt < 2; mt++) {
            const int row0 = blockIdx.y * 128 + wm + mt * 16 + g;
#pragma unroll
            for (int nt = 0; nt < 8; nt++) {
                const int col = colbase + nt * 8 + tig * 2;
                *(float2*)(C + (size_t)row0 * N + col) =
                    make_float2(acc[mt][nt][0], acc[mt][nt][1]);
                *(float2*)(C + (size_t)(row0 + 8) * N + col) =
                    make_float2(acc[mt][nt][2], acc[mt][nt][3]);
            }
        }
    } else {
        // rope + elu + scale: pair (d, d+32) = (acc[..][nt], acc[..][nt+4])
#pragma unroll
        for (int mt = 0; mt < 2; mt++) {
            const int r0 = blockIdx.y * 128 + wm + mt * 16 + g;
#pragma unroll
            for (int half = 0; half < 2; half++) {
                const int row = r0 + half * 8;
                const int n4  = row & (la::SEQ - 1);
#pragma unroll
                for (int nt = 0; nt < 4; nt++) {
#pragma unroll
                    for (int e = 0; e < 2; e++) {
                        const int d  = nt * 8 + tig * 2 + e;
                        const int ai = half * 2 + e;
                        float x1 = acc[mt][nt][ai];
                        float x2 = acc[mt][nt + 4][ai];
                        float2 cs = g_lut[n4 * 32 + d];
                        float o1 = (x1 * cs.x - x2 * cs.y) * ROPE_SC;
                        float o2 = (x1 * cs.y + x2 * cs.x) * ROPE_SC;
                        C[(size_t)row * N + colbase + d]      = tf32f(elu1(o1));
                        C[(size_t)row * N + colbase + d + 32] = tf32f(elu1(o2));
                    }
                }
            }
        }
    }
}

// ---------------- weight transpose (rounds to tf32 at store) ---------------
__global__ __launch_bounds__(256) void transpose_w(const float* __restrict__ src,
                                                   float* __restrict__ dst,
                                                   int R, int Ccols)
{
    __shared__ float t[32][33];
    const int bx = blockIdx.x * 32, by = blockIdx.y * 32;
    const int x = threadIdx.x & 31, y = threadIdx.x >> 5;
#pragma unroll
    for (int i = 0; i < 32; i += 8)
        t[y + i][x] = src[(size_t)(by + y + i) * Ccols + bx + x];
    __syncthreads();
#pragma unroll
    for (int i = 0; i < 32; i += 8)
        dst[(size_t)(bx + y + i) * R + by + x] = tf32f(t[x][y + i]);
}

// ============ chunk_sums: KV_c = K^T @ V (mma), ks = colsum(K) ============
// q/k in g_qkv are ALREADY featurized+tf32 (gemm1 epilogue). Plain staging.
static constexpr int CS_SMEM = 16896 * 4;

__global__ __launch_bounds__(256) void chunk_sums()
{
    extern __shared__ float sm[];
    float* sKT = sm;          // [d][t]
    float* sVT = sm + 8448;   // [m][t]

    const int c  = blockIdx.x;
    const int bh = blockIdx.y;
    const int b  = bh >> 4, h = bh & 15;
    const int tid = threadIdx.x;
    const int wid = tid >> 5, lane = tid & 31;
    const int g = lane >> 2, tig = lane & 3;

    const size_t rowbase = (size_t)(b * la::SEQ + c * la::CHUNK) * 3072 + h * 64;
    const float* kg = g_qkv + rowbase + 1024;
    const float* vg = g_qkv + rowbase + 2048;

#pragma unroll
    for (int i = 0; i < 8; i++) {
        int idx = i * 256 + tid;
        int t = idx >> 4, m0 = (idx & 15) << 2;
        float4 k4 = *(const float4*)(kg + (size_t)t * 3072 + m0);
        sKT[(m0 + 0) * 132 + t] = k4.x;
        sKT[(m0 + 1) * 132 + t] = k4.y;
        sKT[(m0 + 2) * 132 + t] = k4.z;
        sKT[(m0 + 3) * 132 + t] = k4.w;
        float4 v4 = *(const float4*)(vg + (size_t)t * 3072 + m0);
        sVT[(m0 + 0) * 132 + t] = tf32f(v4.x);
        sVT[(m0 + 1) * 132 + t] = tf32f(v4.y);
        sVT[(m0 + 2) * 132 + t] = tf32f(v4.z);
        sVT[(m0 + 3) * 132 + t] = tf32f(v4.w);
    }
    __syncthreads();

    const int wm = (wid & 3) * 16, wn = (wid >> 2) * 32;
    const uint32_t* uK = (const uint32_t*)sKT;
    const uint32_t* uV = (const uint32_t*)sVT;
    float acc[4][4];
#pragma unroll
    for (int nt = 0; nt < 4; nt++)
#pragma unroll
        for (int i = 0; i < 4; i++) acc[nt][i] = 0.f;

#pragma unroll
    for (int ks = 0; ks < 16; ks++) {
        const int kb = ks * 8;
        uint32_t af[4];
        af[0] = uK[(wm + g) * 132 + kb + tig];
        af[1] = uK[(wm + g + 8) * 132 + kb + tig];
        af[2] = uK[(wm + g) * 132 + kb + tig + 4];
        af[3] = uK[(wm + g + 8) * 132 + kb + tig + 4];
#pragma unroll
        for (int nt = 0; nt < 4; nt++) {
            int n = wn + nt * 8 + g;
            uint32_t b0 = uV[n * 132 + kb + tig];
            uint32_t b1 = uV[n * 132 + kb + tig + 4];
            MMA_TF32(acc[nt], af, b0, b1);
        }
    }
    float* outp = g_ckv + ((size_t)bh * la::NCHUNK + c) * 4096;
#pragma unroll
    for (int nt = 0; nt < 4; nt++) {
        int d = wm + g, m = wn + nt * 8 + tig * 2;
        *(float2*)(outp + d * 64 + m)       = make_float2(acc[nt][0], acc[nt][1]);
        *(float2*)(outp + (d + 8) * 64 + m) = make_float2(acc[nt][2], acc[nt][3]);
    }
    if (tid < 64) {
        float s = 0.f;
        for (int t = 0; t < 128; t++) s += sKT[tid * 132 + t];
        g_cks[((size_t)bh * la::NCHUNK + c) * 64 + tid] = s;
    }
}

// ---------------- exclusive prefix over chunks -----------------------------
__global__ __launch_bounds__(256) void prefix_scan()
{
    const int bh  = blockIdx.x;
    const int seg = blockIdx.y;
    const int tid = threadIdx.x;

    float2* base = (float2*)(g_ckv + (size_t)bh * la::NCHUNK * 4096) + seg * 256 + tid;
    float2 vals[la::NCHUNK];
#pragma unroll
    for (int c = 0; c < la::NCHUNK; c++) vals[c] = base[c * 2048];
    float2 run = make_float2(0.f, 0.f);
#pragma unroll
    for (int c = 0; c < la::NCHUNK; c++) {
        float2 t = vals[c];
        vals[c] = run;
        run.x += t.x; run.y += t.y;
    }
#pragma unroll
    for (int c = 0; c < la::NCHUNK; c++) base[c * 2048] = vals[c];

    if (seg == 0 && tid < 64) {
        float* kb = g_cks + (size_t)bh * la::NCHUNK * 64 + tid;
        float kv[la::NCHUNK];
#pragma unroll
        for (int c = 0; c < la::NCHUNK; c++) kv[c] = kb[c * 64];
        float r = 0.f;
#pragma unroll
        for (int c = 0; c < la::NCHUNK; c++) { float t = kv[c]; kv[c] = r; r += t; }
#pragma unroll
        for (int c = 0; c < la::NCHUNK; c++) kb[c * 64] = kv[c];
    }
}

// ============ chunk_out: mma-based intra + inter ==========================
static constexpr int CO_SMEM = 38848 * 4;

__global__ __launch_bounds__(256) void chunk_out()
{
    extern __shared__ float sm[];
    float* sQ   = sm;             // [r][d]  (68 stride)
    float* sK   = sm + 8704;      // [t][d]  (later sVT)
    float* sVT  = sm + 8704;      // [m][t]  (132 stride)
    float* sS   = sm + 17408;     // [r][j]  (132 stride)
    float* sKVT = sm + 34304;     // [m][d]  (68 stride)
    float* sks  = sm + 38656;
    float* sden = sm + 38720;

    const int c  = blockIdx.x;
    const int bh = blockIdx.y;
    const int b  = bh >> 4, h = bh & 15;
    const int tid = threadIdx.x;
    const int wid = tid >> 5, lane = tid & 31;
    const int g = lane >> 2, tig = lane & 3;

    const size_t rowbase = (size_t)(b * la::SEQ + c * la::CHUNK) * 3072 + h * 64;
    const float* qg = g_qkv + rowbase;
    const float* kg = qg + 1024;
    const float* vg = qg + 2048;

    // plain staging: q,k already featurized+tf32
#pragma unroll
    for (int i = 0; i < 8; i++) {
        int idx = i * 256 + tid;
        int t = idx >> 4, d0 = (idx & 15) << 2;
        *(float4*)(sQ + t * 68 + d0) = *(const float4*)(qg + (size_t)t * 3072 + d0);
        *(float4*)(sK + t * 68 + d0) = *(const float4*)(kg + (size_t)t * 3072 + d0);
    }
    const float* kvg = g_ckv + ((size_t)bh * la::NCHUNK + c) * 4096;
#pragma unroll
    for (int i = 0; i < 4; i++) {
        int idx = i * 256 + tid;
        int d = idx >> 4, m0 = (idx & 15) << 2;
        float4 kv4 = *(const float4*)(kvg + d * 64 + m0);
        sKVT[(m0 + 0) * 68 + d] = tf32f(kv4.x);
        sKVT[(m0 + 1) * 68 + d] = tf32f(kv4.y);
        sKVT[(m0 + 2) * 68 + d] = tf32f(kv4.z);
        sKVT[(m0 + 3) * 68 + d] = tf32f(kv4.w);
    }
    if (tid < 64) sks[tid] = g_cks[((size_t)bh * la::NCHUNK + c) * 64 + tid];
    __syncthreads();

    // stage1: S = Qf @ Kf^T
    {
        const int wm = (wid & 3) * 32, wn = (wid >> 2) * 64;
        const uint32_t* uA = (const uint32_t*)sQ;
        const uint32_t* uB = (const uint32_t*)sK;
        float acc[2][8][4];
#pragma unroll
        for (int mt = 0; mt < 2; mt++)
#pragma unroll
            for (int nt = 0; nt < 8; nt++)
#pragma unroll
                for (int i = 0; i < 4; i++) acc[mt][nt][i] = 0.f;
#pragma unroll
        for (int ks = 0; ks < 8; ks++) {
            const int kb = ks * 8;
            uint32_t af[2][4];
#pragma unroll
            for (int mt = 0; mt < 2; mt++) {
                int r = wm + mt * 16 + g;
                af[mt][0] = uA[r * 68 + kb + tig];
                af[mt][1] = uA[(r + 8) * 68 + kb + tig];
                af[mt][2] = uA[r * 68 + kb + tig + 4];
                af[mt][3] = uA[(r + 8) * 68 + kb + tig + 4];
            }
#pragma unroll
            for (int nt = 0; nt < 8; nt++) {
                int n = wn + nt * 8 + g;
                uint32_t b0 = uB[n * 68 + kb + tig];
                uint32_t b1 = uB[n * 68 + kb + tig + 4];
                MMA_TF32(acc[0][nt], af[0], b0, b1);
                MMA_TF32(acc[1][nt], af[1], b0, b1);
            }
        }
        __syncthreads();

#pragma unroll
        for (int mt = 0; mt < 2; mt++) {
            int r0 = wm + mt * 16 + g, r1 = r0 + 8;
#pragma unroll
            for (int nt = 0; nt < 8; nt++) {
                int j0 = wn + nt * 8 + tig * 2;
                float v00 = (j0     <= r0) ? tf32f(acc[mt][nt][0]) : 0.f;
                float v01 = (j0 + 1 <= r0) ? tf32f(acc[mt][nt][1]) : 0.f;
                float v10 = (j0     <= r1) ? tf32f(acc[mt][nt][2]) : 0.f;
                float v11 = (j0 + 1 <= r1) ? tf32f(acc[mt][nt][3]) : 0.f;
                *(float2*)(sS + r0 * 132 + j0) = make_float2(v00, v01);
                *(float2*)(sS + r1 * 132 + j0) = make_float2(v10, v11);
            }
        }
    }
#pragma unroll
    for (int i = 0; i < 8; i++) {
        int idx = i * 256 + tid;
        int t = idx >> 4, m0 = (idx & 15) << 2;
        float4 v4 = *(const float4*)(vg + (size_t)t * 3072 + m0);
        sVT[(m0 + 0) * 132 + t] = tf32f(v4.x);
        sVT[(m0 + 1) * 132 + t] = tf32f(v4.y);
        sVT[(m0 + 2) * 132 + t] = tf32f(v4.z);
        sVT[(m0 + 3) * 132 + t] = tf32f(v4.w);
    }
    __syncthreads();

    if (tid < 128) {
        const int r = tid;
        float s = 0.f;
        for (int j = 0; j < 128; j++) s += sS[r * 132 + j];
        for (int d = 0; d < 64; d++) s = fmaf(sQ[r * 68 + d], sks[d], s);
        sden[r] = fmaxf(s, 1e-6f);
    }
    __syncthreads();

    // stage2: out = S_masked @ V + Qf @ KV^T
    {
        const int wm = (wid & 3) * 32, wn = (wid >> 2) * 32;
        const uint32_t* uS = (const uint32_t*)sS;
        const uint32_t* uV = (const uint32_t*)sVT;
        const uint32_t* uQ = (const uint32_t*)sQ;
        const uint32_t* uKV = (const uint32_t*)sKVT;
        float acc[2][4][4];
#pragma unroll
        for (int mt = 0; mt < 2; mt++)
#pragma unroll
            for (int nt = 0; nt < 4; nt++)
#pragma unroll
                for (int i = 0; i < 4; i++) acc[mt][nt][i] = 0.f;

#pragma unroll
        for (int ks = 0; ks < 16; ks++) {
            const int kb = ks * 8;
            uint32_t af[2][4];
#pragma unroll
            for (int mt = 0; mt < 2; mt++) {
                int r = wm + mt * 16 + g;
                af[mt][0] = uS[r * 132 + kb + tig];
                af[mt][1] = uS[(r + 8) * 132 + kb + tig];
                af[mt][2] = uS[r * 132 + kb + tig + 4];
                af[mt][3] = uS[(r + 8) * 132 + kb + tig + 4];
            }
#pragma unroll
            for (int nt = 0; nt < 4; nt++) {
                int n = wn + nt * 8 + g;
                uint32_t b0 = uV[n * 132 + kb + tig];
                uint32_t b1 = uV[n * 132 + kb + tig + 4];
                MMA_TF32(acc[0][nt], af[0], b0, b1);
                MMA_TF32(acc[1][nt], af[1], b0, b1);
            }
        }
#pragma unroll
        for (int ks = 0; ks < 8; ks++) {
            const int kb = ks * 8;
            uint32_t af[2][4];
#pragma unroll
            for (int mt = 0; mt < 2; mt++) {
                int r = wm + mt * 16 + g;
                af[mt][0] = uQ[r * 68 + kb + tig];
                af[mt][1] = uQ[(r + 8) * 68 + kb + tig];
                af[mt][2] = uQ[r * 68 + kb + tig + 4];
                af[mt][3] = uQ[(r + 8) * 68 + kb + tig + 4];
            }
#pragma unroll
            for (int nt = 0; nt < 4; nt++) {
                int n = wn + nt * 8 + g;
                uint32_t b0 = uKV[n * 68 + kb + tig];
                uint32_t b1 = uKV[n * 68 + kb + tig + 4];
                MMA_TF32(acc[0][nt], af[0], b0, b1);
                MMA_TF32(acc[1][nt], af[1], b0, b1);
            }
        }

        // epilogue: divide, round to tf32 (feeds the pre-rounded GEMM)
#pragma unroll
        for (int mt = 0; mt < 2; mt++) {
            int r0 = wm + mt * 16 + g, r1 = r0 + 8;
            float inv0 = 1.0f / sden[r0];
            float inv1 = 1.0f / sden[r1];
            float* o0 = g_attn + (size_t)(b * la::SEQ + c * la::CHUNK + r0) * 1024 + h * 64;
            float* o1 = g_attn + (size_t)(b * la::SEQ + c * la::CHUNK + r1) * 1024 + h * 64;
#pragma unroll
            for (int nt = 0; nt < 4; nt++) {
                int m = wn + nt * 8 + tig * 2;
                *(float2*)(o0 + m) = make_float2(tf32f(acc[mt][nt][0] * inv0),
                                                 tf32f(acc[mt][nt][1] * inv0));
                *(float2*)(o1 + m) = make_float2(tf32f(acc[mt][nt][2] * inv1),
                                                 tf32f(acc[mt][nt][3] * inv1));
            }
        }
    }
}

// ---------------- launch ----------------
extern "C" void kernel_launch(void* const* d_in, const int* in_sizes, int n_in,
                              void* d_out, int out_size)
{
    const float* x    = (const float*)d_in[0];
    const float* wqkv = (const float*)d_in[1];
    const float* wout = (const float*)d_in[2];
    float*       out  = (float*)d_out;

    float *qkv, *attn, *wT, *xr;
    cudaGetSymbolAddress((void**)&qkv, g_qkv);
    cudaGetSymbolAddress((void**)&attn, g_attn);
    cudaGetSymbolAddress((void**)&wT, g_wT);
    cudaGetSymbolAddress((void**)&xr, g_xr);
    float* wqkvT = wT;
    float* woutT = wT + 3072 * 1024;

    cudaFuncSetAttribute(gemm_mma,   cudaFuncAttributeMaxDynamicSharedMemorySize, GM_SMEM);
    cudaFuncSetAttribute(chunk_sums, cudaFuncAttributeMaxDynamicSharedMemorySize, CS_SMEM);
    cudaFuncSetAttribute(chunk_out,  cudaFuncAttributeMaxDynamicSharedMemorySize, CO_SMEM);

    // 0) rope LUT, tf32-rounded weight transposes, tf32-rounded x
    rope_lut_build<<<la::SEQ, 32>>>();
    transpose_w<<<dim3(3072 / 32, 1024 / 32), 256>>>(wqkv, wqkvT, 1024, 3072);
    transpose_w<<<dim3(1024 / 32, 1024 / 32), 256>>>(wout, woutT, 1024, 1024);
    round_tf32_k<<<la::ROWS * la::DIM / 1024, 256>>>(x, xr);

    // 1) qkv = x @ w_qkv, rope+elu fused into q/k epilogue
    gemm_mma<<<dim3(3072 / 128, la::ROWS / 128), 256, GM_SMEM>>>(xr, wqkvT, qkv,
                                                                 la::ROWS, 3072, 1024, 1);

    // 2) per-chunk KV sums
    dim3 g3(la::NCHUNK, la::NB * la::NHEADS);
    chunk_sums<<<g3, 256, CS_SMEM>>>();

    // 3) exclusive prefix over chunks
    prefix_scan<<<dim3(la::NB * la::NHEADS, 8), 256>>>();

    // 4) per-chunk outputs
    chunk_out<<<g3, 256, CO_SMEM>>>();

    // 5) out = attn @ w_out
    gemm_mma<<<dim3(1024 / 128, la::ROWS / 128), 256, GM_SMEM>>>(attn, woutT, out,
                                                                 la::ROWS, 1024, 1024, 0);
}

// round 11
// speedup vs baseline: 2.4770x; 1.2982x over previous
#include <cuda_runtime.h>
#include <cuda_fp16.h>
#include <math.h>
#include <stdint.h>

// ---------------- problem constants ----------------
namespace la {
constexpr int DIM    = 1024;
constexpr int NHEADS = 16;
constexpr int HD     = 64;
constexpr int NB     = 4;
constexpr int SEQ    = 4096;
constexpr int ROWS   = NB * SEQ; // 16384
constexpr int CHUNK  = 128;
constexpr int NCHUNK = SEQ / CHUNK; // 32
}

// ---------------- scratch (device globals: allocation-free) ----------------
__device__ float  g_qkv[(size_t)la::ROWS * 3 * la::DIM];          // fp32 (tf32 vals)
__device__ __half g_attn[(size_t)la::ROWS * la::DIM];             // fp16
__device__ float  g_ckv[(size_t)la::NB * la::NHEADS * la::NCHUNK * la::HD * la::HD];
__device__ float  g_cks[(size_t)la::NB * la::NHEADS * la::NCHUNK * la::HD];
__device__ __half g_wTh[3072 * 1024 + 1024 * 1024];               // fp16 transposed weights
__device__ __half g_xh[(size_t)la::ROWS * la::DIM];               // fp16 x
__device__ float2 g_lut[la::SEQ * 32];

// ---------------- helpers ----------------
__device__ __forceinline__ uint32_t cvt_tf32(float f) {
    uint32_t u;
    asm("cvt.rna.tf32.f32 %0, %1;" : "=r"(u) : "f"(f));
    return u;
}
__device__ __forceinline__ float tf32f(float f) { return __uint_as_float(cvt_tf32(f)); }

__device__ __forceinline__ uint32_t smem_u32(const void* p) {
    uint32_t a;
    asm("{ .reg .u64 t; cvta.to.shared.u64 t, %1; cvt.u32.u64 %0, t; }" : "=r"(a) : "l"(p));
    return a;
}

#define MMA_TF32(c, a, b0, b1)                                              \
    asm volatile("mma.sync.aligned.m16n8k8.row.col.f32.tf32.tf32.f32 "      \
                 "{%0,%1,%2,%3},{%4,%5,%6,%7},{%8,%9},{%0,%1,%2,%3};"       \
                 : "+f"((c)[0]), "+f"((c)[1]), "+f"((c)[2]), "+f"((c)[3])   \
                 : "r"((a)[0]), "r"((a)[1]), "r"((a)[2]), "r"((a)[3]),      \
                   "r"(b0), "r"(b1))

#define MMA_F16(c, a, b0, b1)                                               \
    asm volatile("mma.sync.aligned.m16n8k16.row.col.f32.f16.f16.f32 "       \
                 "{%0,%1,%2,%3},{%4,%5,%6,%7},{%8,%9},{%0,%1,%2,%3};"       \
                 : "+f"((c)[0]), "+f"((c)[1]), "+f"((c)[2]), "+f"((c)[3])   \
                 : "r"((a)[0]), "r"((a)[1]), "r"((a)[2]), "r"((a)[3]),      \
                   "r"(b0), "r"(b1))

#define CP_ASYNC16(dst, src) \
    asm volatile("cp.async.cg.shared.global [%0], [%1], 16;" :: "r"(dst), "l"(src) : "memory")
#define CP_COMMIT  asm volatile("cp.async.commit_group;" ::: "memory")
#define CP_WAIT1   asm volatile("cp.async.wait_group 1;" ::: "memory")

__device__ __forceinline__ float elu1(float z) {
    return (z > 0.f) ? (z + 1.0f) : expf(z);
}
constexpr float ROPE_SC = 0.35355339059327373f; // 64^(-1/4)

// ============ rope LUT build ==============================================
__global__ void rope_lut_build()
{
    const int n = blockIdx.x, lane = threadIdx.x;
    float pw   = powf(10000.0f, (float)lane * (1.0f / 32.0f));
    float invf = 1.0f / pw;
    float ang  = (float)n * invf;
    float s, c;
    sincosf(ang, &s, &c);
    g_lut[n * 32 + lane] = make_float2(c, s);
}

// ============ fp32 -> fp16 round pass =====================================
__global__ __launch_bounds__(256) void round_f16_k(const float* __restrict__ src,
                                                   __half* __restrict__ dst)
{
    const size_t i = ((size_t)blockIdx.x * 256 + threadIdx.x) * 8;
    float4 v1 = *(const float4*)(src + i);
    float4 v2 = *(const float4*)(src + i + 4);
    __half2 h[4] = { __floats2half2_rn(v1.x, v1.y), __floats2half2_rn(v1.z, v1.w),
                     __floats2half2_rn(v2.x, v2.y), __floats2half2_rn(v2.z, v2.w) };
    *(uint4*)(dst + i) = *(uint4*)h;
}

// ============ fp16 GEMM (R10 pipeline): C = A[M,K] @ Bt[N,K]^T ============
// 128x128 CTA tile, BK=32 (2 x k16 MMA steps), 256 threads, 8 warps,
// warp tile 32x64, occ 2. cp.async 3-stage. Row stride 40 halves (20 uints)
// -> LDS banks 20g+tig cover all 32: conflict-free.
// feat=1: rope+elu+scale fused into q/k epilogue (fp32 out to g_qkv).
static constexpr int GH_STRU   = 20;                 // uints per row
static constexpr int GH_ROWB   = 80;                 // bytes per row
static constexpr int GH_TILE_B = 128 * GH_ROWB;      // 10240 B per matrix
static constexpr int GH_STAGE  = 2 * GH_TILE_B;      // 20480 B
static constexpr int GH_SMEM   = 3 * GH_STAGE;       // 61440 B

__global__ __launch_bounds__(256, 2) void gemm_h(const __half* __restrict__ A,
                                                 const __half* __restrict__ Bt,
                                                 float* __restrict__ C,
                                                 int M, int N, int K, int feat)
{
    extern __shared__ char smc[];
    const uint32_t sbase = smem_u32(smc);

    const int tid  = threadIdx.x;
    const int wid  = tid >> 5, lane = tid & 31;
    const int g    = lane >> 2, tig = lane & 3;
    const int wm   = (wid & 3) * 32, wn = (wid >> 2) * 64;

    const __half* Ab = A  + (size_t)blockIdx.y * 128 * K;
    const __half* Bb = Bt + (size_t)blockIdx.x * 128 * K;

    const int lr = tid >> 1, lqh = (tid & 1) * 16;   // row, half-offset

    auto load_stage = [&](int s, int kc) {
        const uint32_t base = sbase + s * GH_STAGE;
        const uint32_t off  = lr * GH_ROWB + lqh * 2;
        const __half* sa = Ab + (size_t)lr * K + kc * 32 + lqh;
        const __half* sb = Bb + (size_t)lr * K + kc * 32 + lqh;
        CP_ASYNC16(base + off,                 sa);
        CP_ASYNC16(base + off + 16,            sa + 8);
        CP_ASYNC16(base + GH_TILE_B + off,      sb);
        CP_ASYNC16(base + GH_TILE_B + off + 16, sb + 8);
        CP_COMMIT;
    };

    float acc[2][8][4];
#pragma unroll
    for (int mt = 0; mt < 2; mt++)
#pragma unroll
        for (int nt = 0; nt < 8; nt++)
#pragma unroll
            for (int i = 0; i < 4; i++) acc[mt][nt][i] = 0.f;

    auto compute = [&](int buf) {
        const uint32_t* uA = (const uint32_t*)(smc + buf * GH_STAGE);
        const uint32_t* uB = uA + 128 * GH_STRU;
#pragma unroll
        for (int ks = 0; ks < 2; ks++) {
            const int kb = ks * 8;
            uint32_t af[2][4];
#pragma unroll
            for (int mt = 0; mt < 2; mt++) {
                int r = wm + mt * 16 + g;
                af[mt][0] = uA[r * GH_STRU + kb + tig];
                af[mt][1] = uA[(r + 8) * GH_STRU + kb + tig];
                af[mt][2] = uA[r * GH_STRU + kb + tig + 4];
                af[mt][3] = uA[(r + 8) * GH_STRU + kb + tig + 4];
            }
#pragma unroll
            for (int nt = 0; nt < 8; nt++) {
                int n = wn + nt * 8 + g;
                uint32_t b0 = uB[n * GH_STRU + kb + tig];
                uint32_t b1 = uB[n * GH_STRU + kb + tig + 4];
                MMA_F16(acc[0][nt], af[0], b0, b1);
                MMA_F16(acc[1][nt], af[1], b0, b1);
            }
        }
    };

    load_stage(0, 0);
    load_stage(1, 1);

    const int KC = K >> 5;
    for (int kc = 0; kc < KC; kc++) {
        CP_WAIT1;
        __syncthreads();
        compute(kc % 3);
        if (kc + 2 < KC) load_stage((kc + 2) % 3, kc + 2);
        else             CP_COMMIT;   // keep group count consistent
    }

    // ---------------- epilogue ----------------
    const int colbase = blockIdx.x * 128 + wn;   // 64-aligned
    const int which   = colbase >> 10;           // 0=q 1=k 2=v
    const bool dofeat = feat && (which < 2);

    if (!dofeat) {
#pragma unroll
        for (int mt = 0; mt < 2; mt++) {
            const int row0 = blockIdx.y * 128 + wm + mt * 16 + g;
#pragma unroll
            for (int nt = 0; nt < 8; nt++) {
                const int col = colbase + nt * 8 + tig * 2;
                *(float2*)(C + (size_t)row0 * N + col) =
                    make_float2(acc[mt][nt][0], acc[mt][nt][1]);
                *(float2*)(C + (size_t)(row0 + 8) * N + col) =
                    make_float2(acc[mt][nt][2], acc[mt][nt][3]);
            }
        }
    } else {
        // rope + elu + scale: pair (d, d+32) = (acc[..][nt], acc[..][nt+4])
#pragma unroll
        for (int mt = 0; mt < 2; mt++) {
            const int r0 = blockIdx.y * 128 + wm + mt * 16 + g;
#pragma unroll
            for (int half = 0; half < 2; half++) {
                const int row = r0 + half * 8;
                const int n4  = row & (la::SEQ - 1);
#pragma unroll
                for (int nt = 0; nt < 4; nt++) {
#pragma unroll
                    for (int e = 0; e < 2; e++) {
                        const int d  = nt * 8 + tig * 2 + e;
                        const int ai = half * 2 + e;
                        float x1 = acc[mt][nt][ai];
                        float x2 = acc[mt][nt + 4][ai];
                        float2 cs = g_lut[n4 * 32 + d];
                        float o1 = (x1 * cs.x - x2 * cs.y) * ROPE_SC;
                        float o2 = (x1 * cs.y + x2 * cs.x) * ROPE_SC;
                        C[(size_t)row * N + colbase + d]      = tf32f(elu1(o1));
                        C[(size_t)row * N + colbase + d + 32] = tf32f(elu1(o2));
                    }
                }
            }
        }
    }
}

// ---------------- weight transpose -> fp16 ---------------------------------
__global__ __launch_bounds__(256) void transpose_w_h(const float* __restrict__ src,
                                                     __half* __restrict__ dst,
                                                     int R, int Ccols)
{
    __shared__ float t[32][33];
    const int bx = blockIdx.x * 32, by = blockIdx.y * 32;
    const int x = threadIdx.x & 31, y = threadIdx.x >> 5;
#pragma unroll
    for (int i = 0; i < 32; i += 8)
        t[y + i][x] = src[(size_t)(by + y + i) * Ccols + bx + x];
    __syncthreads();
#pragma unroll
    for (int i = 0; i < 32; i += 8)
        dst[(size_t)(bx + y + i) * R + by + x] = __float2half_rn(t[x][y + i]);
}

// ============ chunk_sums: KV_c = K^T @ V (tf32 mma), ks = colsum(K) =======
static constexpr int CS_SMEM = 16896 * 4;

__global__ __launch_bounds__(256) void chunk_sums()
{
    extern __shared__ float sm[];
    float* sKT = sm;          // [d][t]
    float* sVT = sm + 8448;   // [m][t]

    const int c  = blockIdx.x;
    const int bh = blockIdx.y;
    const int b  = bh >> 4, h = bh & 15;
    const int tid = threadIdx.x;
    const int wid = tid >> 5, lane = tid & 31;
    const int g = lane >> 2, tig = lane & 3;

    const size_t rowbase = (size_t)(b * la::SEQ + c * la::CHUNK) * 3072 + h * 64;
    const float* kg = g_qkv + rowbase + 1024;
    const float* vg = g_qkv + rowbase + 2048;

#pragma unroll
    for (int i = 0; i < 8; i++) {
        int idx = i * 256 + tid;
        int t = idx >> 4, m0 = (idx & 15) << 2;
        float4 k4 = *(const float4*)(kg + (size_t)t * 3072 + m0);
        sKT[(m0 + 0) * 132 + t] = k4.x;
        sKT[(m0 + 1) * 132 + t] = k4.y;
        sKT[(m0 + 2) * 132 + t] = k4.z;
        sKT[(m0 + 3) * 132 + t] = k4.w;
        float4 v4 = *(const float4*)(vg + (size_t)t * 3072 + m0);
        sVT[(m0 + 0) * 132 + t] = tf32f(v4.x);
        sVT[(m0 + 1) * 132 + t] = tf32f(v4.y);
        sVT[(m0 + 2) * 132 + t] = tf32f(v4.z);
        sVT[(m0 + 3) * 132 + t] = tf32f(v4.w);
    }
    __syncthreads();

    const int wm = (wid & 3) * 16, wn = (wid >> 2) * 32;
    const uint32_t* uK = (const uint32_t*)sKT;
    const uint32_t* uV = (const uint32_t*)sVT;
    float acc[4][4];
#pragma unroll
    for (int nt = 0; nt < 4; nt++)
#pragma unroll
        for (int i = 0; i < 4; i++) acc[nt][i] = 0.f;

#pragma unroll
    for (int ks = 0; ks < 16; ks++) {
        const int kb = ks * 8;
        uint32_t af[4];
        af[0] = uK[(wm + g) * 132 + kb + tig];
        af[1] = uK[(wm + g + 8) * 132 + kb + tig];
        af[2] = uK[(wm + g) * 132 + kb + tig + 4];
        af[3] = uK[(wm + g + 8) * 132 + kb + tig + 4];
#pragma unroll
        for (int nt = 0; nt < 4; nt++) {
            int n = wn + nt * 8 + g;
            uint32_t b0 = uV[n * 132 + kb + tig];
            uint32_t b1 = uV[n * 132 + kb + tig + 4];
            MMA_TF32(acc[nt], af, b0, b1);
        }
    }
    float* outp = g_ckv + ((size_t)bh * la::NCHUNK + c) * 4096;
#pragma unroll
    for (int nt = 0; nt < 4; nt++) {
        int d = wm + g, m = wn + nt * 8 + tig * 2;
        *(float2*)(outp + d * 64 + m)       = make_float2(acc[nt][0], acc[nt][1]);
        *(float2*)(outp + (d + 8) * 64 + m) = make_float2(acc[nt][2], acc[nt][3]);
    }
    if (tid < 64) {
        float s = 0.f;
        for (int t = 0; t < 128; t++) s += sKT[tid * 132 + t];
        g_cks[((size_t)bh * la::NCHUNK + c) * 64 + tid] = s;
    }
}

// ---------------- exclusive prefix over chunks -----------------------------
__global__ __launch_bounds__(256) void prefix_scan()
{
    const int bh  = blockIdx.x;
    const int seg = blockIdx.y;
    const int tid = threadIdx.x;

    float2* base = (float2*)(g_ckv + (size_t)bh * la::NCHUNK * 4096) + seg * 256 + tid;
    float2 vals[la::NCHUNK];
#pragma unroll
    for (int c = 0; c < la::NCHUNK; c++) vals[c] = base[c * 2048];
    float2 run = make_float2(0.f, 0.f);
#pragma unroll
    for (int c = 0; c < la::NCHUNK; c++) {
        float2 t = vals[c];
        vals[c] = run;
        run.x += t.x; run.y += t.y;
    }
#pragma unroll
    for (int c = 0; c < la::NCHUNK; c++) base[c * 2048] = vals[c];

    if (seg == 0 && tid < 64) {
        float* kb = g_cks + (size_t)bh * la::NCHUNK * 64 + tid;
        float kv[la::NCHUNK];
#pragma unroll
        for (int c = 0; c < la::NCHUNK; c++) kv[c] = kb[c * 64];
        float r = 0.f;
#pragma unroll
        for (int c = 0; c < la::NCHUNK; c++) { float t = kv[c]; kv[c] = r; r += t; }
#pragma unroll
        for (int c = 0; c < la::NCHUNK; c++) kb[c * 64] = kv[c];
    }
}

// ============ chunk_out: mma-based intra + inter (tf32), fp16 attn out ====
static constexpr int CO_SMEM = 38848 * 4;

__global__ __launch_bounds__(256) void chunk_out()
{
    extern __shared__ float sm[];
    float* sQ   = sm;             // [r][d]  (68 stride)
    float* sK   = sm + 8704;      // [t][d]  (later sVT)
    float* sVT  = sm + 8704;      // [m][t]  (132 stride)
    float* sS   = sm + 17408;     // [r][j]  (132 stride)
    float* sKVT = sm + 34304;     // [m][d]  (68 stride)
    float* sks  = sm + 38656;
    float* sden = sm + 38720;

    const int c  = blockIdx.x;
    const int bh = blockIdx.y;
    const int b  = bh >> 4, h = bh & 15;
    const int tid = threadIdx.x;
    const int wid = tid >> 5, lane = tid & 31;
    const int g = lane >> 2, tig = lane & 3;

    const size_t rowbase = (size_t)(b * la::SEQ + c * la::CHUNK) * 3072 + h * 64;
    const float* qg = g_qkv + rowbase;
    const float* kg = qg + 1024;
    const float* vg = qg + 2048;

    // plain staging: q,k already featurized+tf32
#pragma unroll
    for (int i = 0; i < 8; i++) {
        int idx = i * 256 + tid;
        int t = idx >> 4, d0 = (idx & 15) << 2;
        *(float4*)(sQ + t * 68 + d0) = *(const float4*)(qg + (size_t)t * 3072 + d0);
        *(float4*)(sK + t * 68 + d0) = *(const float4*)(kg + (size_t)t * 3072 + d0);
    }
    const float* kvg = g_ckv + ((size_t)bh * la::NCHUNK + c) * 4096;
#pragma unroll
    for (int i = 0; i < 4; i++) {
        int idx = i * 256 + tid;
        int d = idx >> 4, m0 = (idx & 15) << 2;
        float4 kv4 = *(const float4*)(kvg + d * 64 + m0);
        sKVT[(m0 + 0) * 68 + d] = tf32f(kv4.x);
        sKVT[(m0 + 1) * 68 + d] = tf32f(kv4.y);
        sKVT[(m0 + 2) * 68 + d] = tf32f(kv4.z);
        sKVT[(m0 + 3) * 68 + d] = tf32f(kv4.w);
    }
    if (tid < 64) sks[tid] = g_cks[((size_t)bh * la::NCHUNK + c) * 64 + tid];
    __syncthreads();

    // stage1: S = Qf @ Kf^T
    {
        const int wm = (wid & 3) * 32, wn = (wid >> 2) * 64;
        const uint32_t* uA = (const uint32_t*)sQ;
        const uint32_t* uB = (const uint32_t*)sK;
        float acc[2][8][4];
#pragma unroll
        for (int mt = 0; mt < 2; mt++)
#pragma unroll
            for (int nt = 0; nt < 8; nt++)
#pragma unroll
                for (int i = 0; i < 4; i++) acc[mt][nt][i] = 0.f;
#pragma unroll
        for (int ks = 0; ks < 8; ks++) {
            const int kb = ks * 8;
            uint32_t af[2][4];
#pragma unroll
            for (int mt = 0; mt < 2; mt++) {
                int r = wm + mt * 16 + g;
                af[mt][0] = uA[r * 68 + kb + tig];
                af[mt][1] = uA[(r + 8) * 68 + kb + tig];
                af[mt][2] = uA[r * 68 + kb + tig + 4];
                af[mt][3] = uA[(r + 8) * 68 + kb + tig + 4];
            }
#pragma unroll
            for (int nt = 0; nt < 8; nt++) {
                int n = wn + nt * 8 + g;
                uint32_t b0 = uB[n * 68 + kb + tig];
                uint32_t b1 = uB[n * 68 + kb + tig + 4];
                MMA_TF32(acc[0][nt], af[0], b0, b1);
                MMA_TF32(acc[1][nt], af[1], b0, b1);
            }
        }
        __syncthreads();

#pragma unroll
        for (int mt = 0; mt < 2; mt++) {
            int r0 = wm + mt * 16 + g, r1 = r0 + 8;
#pragma unroll
            for (int nt = 0; nt < 8; nt++) {
                int j0 = wn + nt * 8 + tig * 2;
                float v00 = (j0     <= r0) ? tf32f(acc[mt][nt][0]) : 0.f;
                float v01 = (j0 + 1 <= r0) ? tf32f(acc[mt][nt][1]) : 0.f;
                float v10 = (j0     <= r1) ? tf32f(acc[mt][nt][2]) : 0.f;
                float v11 = (j0 + 1 <= r1) ? tf32f(acc[mt][nt][3]) : 0.f;
                *(float2*)(sS + r0 * 132 + j0) = make_float2(v00, v01);
                *(float2*)(sS + r1 * 132 + j0) = make_float2(v10, v11);
            }
        }
    }
#pragma unroll
    for (int i = 0; i < 8; i++) {
        int idx = i * 256 + tid;
        int t = idx >> 4, m0 = (idx & 15) << 2;
        float4 v4 = *(const float4*)(vg + (size_t)t * 3072 + m0);
        sVT[(m0 + 0) * 132 + t] = tf32f(v4.x);
        sVT[(m0 + 1) * 132 + t] = tf32f(v4.y);
        sVT[(m0 + 2) * 132 + t] = tf32f(v4.z);
        sVT[(m0 + 3) * 132 + t] = tf32f(v4.w);
    }
    __syncthreads();

    if (tid < 128) {
        const int r = tid;
        float s = 0.f;
        for (int j = 0; j < 128; j++) s += sS[r * 132 + j];
        for (int d = 0; d < 64; d++) s = fmaf(sQ[r * 68 + d], sks[d], s);
        sden[r] = fmaxf(s, 1e-6f);
    }
    __syncthreads();

    // stage2: out = S_masked @ V + Qf @ KV^T
    {
        const int wm = (wid & 3) * 32, wn = (wid >> 2) * 32;
        const uint32_t* uS = (const uint32_t*)sS;
        const uint32_t* uV = (const uint32_t*)sVT;
        const uint32_t* uQ = (const uint32_t*)sQ;
        const uint32_t* uKV = (const uint32_t*)sKVT;
        float acc[2][4][4];
#pragma unroll
        for (int mt = 0; mt < 2; mt++)
#pragma unroll
            for (int nt = 0; nt < 4; nt++)
#pragma unroll
                for (int i = 0; i < 4; i++) acc[mt][nt][i] = 0.f;

#pragma unroll
        for (int ks = 0; ks < 16; ks++) {
            const int kb = ks * 8;
            uint32_t af[2][4];
#pragma unroll
            for (int mt = 0; mt < 2; mt++) {
                int r = wm + mt * 16 + g;
                af[mt][0] = uS[r * 132 + kb + tig];
                af[mt][1] = uS[(r + 8) * 132 + kb + tig];
                af[mt][2] = uS[r * 132 + kb + tig + 4];
                af[mt][3] = uS[(r + 8) * 132 + kb + tig + 4];
            }
#pragma unroll
            for (int nt = 0; nt < 4; nt++) {
                int n = wn + nt * 8 + g;
                uint32_t b0 = uV[n * 132 + kb + tig];
                uint32_t b1 = uV[n * 132 + kb + tig + 4];
                MMA_TF32(acc[0][nt], af[0], b0, b1);
                MMA_TF32(acc[1][nt], af[1], b0, b1);
            }
        }
#pragma unroll
        for (int ks = 0; ks < 8; ks++) {
            const int kb = ks * 8;
            uint32_t af[2][4];
#pragma unroll
            for (int mt = 0; mt < 2; mt++) {
                int r = wm + mt * 16 + g;
                af[mt][0] = uQ[r * 68 + kb + tig];
                af[mt][1] = uQ[(r + 8) * 68 + kb + tig];
                af[mt][2] = uQ[r * 68 + kb + tig + 4];
                af[mt][3] = uQ[(r + 8) * 68 + kb + tig + 4];
            }
#pragma unroll
            for (int nt = 0; nt < 4; nt++) {
                int n = wn + nt * 8 + g;
                uint32_t b0 = uKV[n * 68 + kb + tig];
                uint32_t b1 = uKV[n * 68 + kb + tig + 4];
                MMA_TF32(acc[0][nt], af[0], b0, b1);
                MMA_TF32(acc[1][nt], af[1], b0, b1);
            }
        }

        // epilogue: divide, write fp16 attn (feeds fp16 gemm2)
#pragma unroll
        for (int mt = 0; mt < 2; mt++) {
            int r0 = wm + mt * 16 + g, r1 = r0 + 8;
            float inv0 = 1.0f / sden[r0];
            float inv1 = 1.0f / sden[r1];
            __half* o0 = g_attn + (size_t)(b * la::SEQ + c * la::CHUNK + r0) * 1024 + h * 64;
            __half* o1 = g_attn + (size_t)(b * la::SEQ + c * la::CHUNK + r1) * 1024 + h * 64;
#pragma unroll
            for (int nt = 0; nt < 4; nt++) {
                int m = wn + nt * 8 + tig * 2;
                *(__half2*)(o0 + m) = __floats2half2_rn(acc[mt][nt][0] * inv0,
                                                        acc[mt][nt][1] * inv0);
                *(__half2*)(o1 + m) = __floats2half2_rn(acc[mt][nt][2] * inv1,
                                                        acc[mt][nt][3] * inv1);
            }
        }
    }
}

// ---------------- launch ----------------
extern "C" void kernel_launch(void* const* d_in, const int* in_sizes, int n_in,
                              void* d_out, int out_size)
{
    const float* x    = (const float*)d_in[0];
    const float* wqkv = (const float*)d_in[1];
    const float* wout = (const float*)d_in[2];
    float*       out  = (float*)d_out;

    float *qkv;
    __half *attn, *wTh, *xh;
    cudaGetSymbolAddress((void**)&qkv, g_qkv);
    cudaGetSymbolAddress((void**)&attn, g_attn);
    cudaGetSymbolAddress((void**)&wTh, g_wTh);
    cudaGetSymbolAddress((void**)&xh, g_xh);
    __half* wqkvTh = wTh;
    __half* woutTh = wTh + 3072 * 1024;

    cudaFuncSetAttribute(gemm_h,     cudaFuncAttributeMaxDynamicSharedMemorySize, GH_SMEM);
    cudaFuncSetAttribute(chunk_sums, cudaFuncAttributeMaxDynamicSharedMemorySize, CS_SMEM);
    cudaFuncSetAttribute(chunk_out,  cudaFuncAttributeMaxDynamicSharedMemorySize, CO_SMEM);

    // 0) rope LUT, fp16 weight transposes, fp16 x
    rope_lut_build<<<la::SEQ, 32>>>();
    transpose_w_h<<<dim3(3072 / 32, 1024 / 32), 256>>>(wqkv, wqkvTh, 1024, 3072);
    transpose_w_h<<<dim3(1024 / 32, 1024 / 32), 256>>>(wout, woutTh, 1024, 1024);
    round_f16_k<<<la::ROWS * la::DIM / 2048, 256>>>(x, xh);

    // 1) qkv = x @ w_qkv (fp16 mma), rope+elu fused into q/k epilogue
    gemm_h<<<dim3(3072 / 128, la::ROWS / 128), 256, GH_SMEM>>>(xh, wqkvTh, qkv,
                                                               la::ROWS, 3072, 1024, 1);

    // 2) per-chunk KV sums (tf32)
    dim3 g3(la::NCHUNK, la::NB * la::NHEADS);
    chunk_sums<<<g3, 256, CS_SMEM>>>();

    // 3) exclusive prefix over chunks
    prefix_scan<<<dim3(la::NB * la::NHEADS, 8), 256>>>();

    // 4) per-chunk outputs (tf32 math, fp16 attn out)
    chunk_out<<<g3, 256, CO_SMEM>>>();

    // 5) out = attn @ w_out (fp16 mma)
    gemm_h<<<dim3(1024 / 128, la::ROWS / 128), 256, GH_SMEM>>>(attn, woutTh, out,
                                                               la::ROWS, 1024, 1024, 0);
}

// round 13
// speedup vs baseline: 2.6571x; 1.0727x over previous
#include <cuda_runtime.h>
#include <cuda_fp16.h>
#include <math.h>
#include <stdint.h>

// ---------------- problem constants ----------------
namespace la {
constexpr int DIM    = 1024;
constexpr int NHEADS = 16;
constexpr int HD     = 64;
constexpr int NB     = 4;
constexpr int SEQ    = 4096;
constexpr int ROWS   = NB * SEQ; // 16384
constexpr int CHUNK  = 128;
constexpr int NCHUNK = SEQ / CHUNK; // 32
}

// ---------------- scratch (device globals: allocation-free) ----------------
__device__ __half g_qkv[(size_t)la::ROWS * 3 * la::DIM];          // fp16 (q,k featurized)
__device__ __half g_attn[(size_t)la::ROWS * la::DIM];             // fp16
__device__ float  g_ckv[(size_t)la::NB * la::NHEADS * la::NCHUNK * la::HD * la::HD];
__device__ float  g_cks[(size_t)la::NB * la::NHEADS * la::NCHUNK * la::HD];
__device__ __half g_wTh[3072 * 1024 + 1024 * 1024];               // fp16 transposed weights
__device__ __half g_xh[(size_t)la::ROWS * la::DIM];               // fp16 x
__device__ float2 g_lut[la::SEQ * 32];

// ---------------- helpers ----------------
__device__ __forceinline__ uint32_t smem_u32(const void* p) {
    uint32_t a;
    asm("{ .reg .u64 t; cvta.to.shared.u64 t, %1; cvt.u32.u64 %0, t; }" : "=r"(a) : "l"(p));
    return a;
}

#define MMA_F16(c, a, b0, b1)                                               \
    asm volatile("mma.sync.aligned.m16n8k16.row.col.f32.f16.f16.f32 "       \
                 "{%0,%1,%2,%3},{%4,%5,%6,%7},{%8,%9},{%0,%1,%2,%3};"       \
                 : "+f"((c)[0]), "+f"((c)[1]), "+f"((c)[2]), "+f"((c)[3])   \
                 : "r"((a)[0]), "r"((a)[1]), "r"((a)[2]), "r"((a)[3]),      \
                   "r"(b0), "r"(b1))

#define CP_ASYNC16(dst, src) \
    asm volatile("cp.async.cg.shared.global [%0], [%1], 16;" :: "r"(dst), "l"(src) : "memory")
#define CP_COMMIT  asm volatile("cp.async.commit_group;" ::: "memory")
#define CP_WAIT1   asm volatile("cp.async.wait_group 1;" ::: "memory")

__device__ __forceinline__ float elu1(float z) {
    return (z > 0.f) ? (z + 1.0f) : expf(z);
}
constexpr float ROPE_SC = 0.35355339059327373f; // 64^(-1/4)

// ============ rope LUT build ==============================================
__global__ void rope_lut_build()
{
    const int n = blockIdx.x, lane = threadIdx.x;
    float pw   = powf(10000.0f, (float)lane * (1.0f / 32.0f));
    float invf = 1.0f / pw;
    float ang  = (float)n * invf;
    float s, c;
    sincosf(ang, &s, &c);
    g_lut[n * 32 + lane] = make_float2(c, s);
}

// ============ fp32 -> fp16 round pass =====================================
__global__ __launch_bounds__(256) void round_f16_k(const float* __restrict__ src,
                                                   __half* __restrict__ dst)
{
    const size_t i = ((size_t)blockIdx.x * 256 + threadIdx.x) * 8;
    float4 v1 = *(const float4*)(src + i);
    float4 v2 = *(const float4*)(src + i + 4);
    __half2 h[4] = { __floats2half2_rn(v1.x, v1.y), __floats2half2_rn(v1.z, v1.w),
                     __floats2half2_rn(v2.x, v2.y), __floats2half2_rn(v2.z, v2.w) };
    *(uint4*)(dst + i) = *(uint4*)h;
}

// ============ fp16 GEMM: C = A[M,K] @ Bt[N,K]^T ===========================
// 128x128 CTA tile, BK=32 (2 x k16 steps), 256 threads, 8 warps,
// warp tile 32x64, occ 2, cp.async 3-stage. Row stride 40 halves (20 uints).
// mode 0: fp32 out to Cf. mode 1: fp16 out to Ch; rope+elu on q/k blocks.
static constexpr int GH_STRU   = 20;
static constexpr int GH_ROWB   = 80;
static constexpr int GH_TILE_B = 128 * GH_ROWB;
static constexpr int GH_STAGE  = 2 * GH_TILE_B;
static constexpr int GH_SMEM   = 3 * GH_STAGE;       // 61440 B

__global__ __launch_bounds__(256, 2) void gemm_h(const __half* __restrict__ A,
                                                 const __half* __restrict__ Bt,
                                                 float* __restrict__ Cf,
                                                 __half* __restrict__ Ch,
                                                 int M, int N, int K, int mode)
{
    extern __shared__ char smc[];
    const uint32_t sbase = smem_u32(smc);

    const int tid  = threadIdx.x;
    const int wid  = tid >> 5, lane = tid & 31;
    const int g    = lane >> 2, tig = lane & 3;
    const int wm   = (wid & 3) * 32, wn = (wid >> 2) * 64;

    const __half* Ab = A  + (size_t)blockIdx.y * 128 * K;
    const __half* Bb = Bt + (size_t)blockIdx.x * 128 * K;

    const int lr = tid >> 1, lqh = (tid & 1) * 16;

    auto load_stage = [&](int s, int kc) {
        const uint32_t base = sbase + s * GH_STAGE;
        const uint32_t off  = lr * GH_ROWB + lqh * 2;
        const __half* sa = Ab + (size_t)lr * K + kc * 32 + lqh;
        const __half* sb = Bb + (size_t)lr * K + kc * 32 + lqh;
        CP_ASYNC16(base + off,                  sa);
        CP_ASYNC16(base + off + 16,             sa + 8);
        CP_ASYNC16(base + GH_TILE_B + off,      sb);
        CP_ASYNC16(base + GH_TILE_B + off + 16, sb + 8);
        CP_COMMIT;
    };

    float acc[2][8][4];
#pragma unroll
    for (int mt = 0; mt < 2; mt++)
#pragma unroll
        for (int nt = 0; nt < 8; nt++)
#pragma unroll
            for (int i = 0; i < 4; i++) acc[mt][nt][i] = 0.f;

    auto compute = [&](int buf) {
        const uint32_t* uA = (const uint32_t*)(smc + buf * GH_STAGE);
        const uint32_t* uB = uA + 128 * GH_STRU;
#pragma unroll
        for (int ks = 0; ks < 2; ks++) {
            const int kb = ks * 8;
            uint32_t af[2][4];
#pragma unroll
            for (int mt = 0; mt < 2; mt++) {
                int r = wm + mt * 16 + g;
                af[mt][0] = uA[r * GH_STRU + kb + tig];
                af[mt][1] = uA[(r + 8) * GH_STRU + kb + tig];
                af[mt][2] = uA[r * GH_STRU + kb + tig + 4];
                af[mt][3] = uA[(r + 8) * GH_STRU + kb + tig + 4];
            }
#pragma unroll
            for (int nt = 0; nt < 8; nt++) {
                int n = wn + nt * 8 + g;
                uint32_t b0 = uB[n * GH_STRU + kb + tig];
                uint32_t b1 = uB[n * GH_STRU + kb + tig + 4];
                MMA_F16(acc[0][nt], af[0], b0, b1);
                MMA_F16(acc[1][nt], af[1], b0, b1);
            }
        }
    };

    load_stage(0, 0);
    load_stage(1, 1);

    const int KC = K >> 5;
    for (int kc = 0; kc < KC; kc++) {
        CP_WAIT1;
        __syncthreads();
        compute(kc % 3);
        if (kc + 2 < KC) load_stage((kc + 2) % 3, kc + 2);
        else             CP_COMMIT;
    }

    // ---------------- epilogue ----------------
    const int colbase = blockIdx.x * 128 + wn;   // 64-aligned
    const int which   = colbase >> 10;           // 0=q 1=k 2=v

    if (mode == 0) {
#pragma unroll
        for (int mt = 0; mt < 2; mt++) {
            const int row0 = blockIdx.y * 128 + wm + mt * 16 + g;
#pragma unroll
            for (int nt = 0; nt < 8; nt++) {
                const int col = colbase + nt * 8 + tig * 2;
                *(float2*)(Cf + (size_t)row0 * N + col) =
                    make_float2(acc[mt][nt][0], acc[mt][nt][1]);
                *(float2*)(Cf + (size_t)(row0 + 8) * N + col) =
                    make_float2(acc[mt][nt][2], acc[mt][nt][3]);
            }
        }
    } else if (which == 2) {
        // v: plain fp16 store
#pragma unroll
        for (int mt = 0; mt < 2; mt++) {
            const int row0 = blockIdx.y * 128 + wm + mt * 16 + g;
#pragma unroll
            for (int nt = 0; nt < 8; nt++) {
                const int col = colbase + nt * 8 + tig * 2;
                *(__half2*)(Ch + (size_t)row0 * N + col) =
                    __floats2half2_rn(acc[mt][nt][0], acc[mt][nt][1]);
                *(__half2*)(Ch + (size_t)(row0 + 8) * N + col) =
                    __floats2half2_rn(acc[mt][nt][2], acc[mt][nt][3]);
            }
        }
    } else {
        // q/k: rope + elu + scale, fp16 store. pair (d, d+32) thread-local.
#pragma unroll
        for (int mt = 0; mt < 2; mt++) {
            const int r0 = blockIdx.y * 128 + wm + mt * 16 + g;
#pragma unroll
            for (int half = 0; half < 2; half++) {
                const int row = r0 + half * 8;
                const int n4  = row & (la::SEQ - 1);
#pragma unroll
                for (int nt = 0; nt < 4; nt++) {
#pragma unroll
                    for (int e = 0; e < 2; e++) {
                        const int d  = nt * 8 + tig * 2 + e;
                        const int ai = half * 2 + e;
                        float x1 = acc[mt][nt][ai];
                        float x2 = acc[mt][nt + 4][ai];
                        float2 cs = g_lut[n4 * 32 + d];
                        float o1 = (x1 * cs.x - x2 * cs.y) * ROPE_SC;
                        float o2 = (x1 * cs.y + x2 * cs.x) * ROPE_SC;
                        Ch[(size_t)row * N + colbase + d]      = __float2half_rn(elu1(o1));
                        Ch[(size_t)row * N + colbase + d + 32] = __float2half_rn(elu1(o2));
                    }
                }
            }
        }
    }
}

// ---------------- weight transpose -> fp16 ---------------------------------
__global__ __launch_bounds__(256) void transpose_w_h(const float* __restrict__ src,
                                                     __half* __restrict__ dst,
                                                     int R, int Ccols)
{
    __shared__ float t[32][33];
    const int bx = blockIdx.x * 32, by = blockIdx.y * 32;
    const int x = threadIdx.x & 31, y = threadIdx.x >> 5;
#pragma unroll
    for (int i = 0; i < 32; i += 8)
        t[y + i][x] = src[(size_t)(by + y + i) * Ccols + bx + x];
    __syncthreads();
#pragma unroll
    for (int i = 0; i < 32; i += 8)
        dst[(size_t)(bx + y + i) * R + by + x] = __float2half_rn(t[x][y + i]);
}

// ============ chunk_sums: KV_c = K^T @ V (fp16 mma), ks = colsum(K) =======
// smem halves: sKT [d=64][t=128] stride 136 | sVT same. 34816 B.
static constexpr int CS_SMEM = 34816;

__global__ __launch_bounds__(256) void chunk_sums()
{
    extern __shared__ __half smh[];
    __half* sKT = smh;          // [d][t]
    __half* sVT = smh + 8704;   // [m][t]

    const int c  = blockIdx.x;
    const int bh = blockIdx.y;
    const int b  = bh >> 4, h = bh & 15;
    const int tid = threadIdx.x;
    const int wid = tid >> 5, lane = tid & 31;
    const int g = lane >> 2, tig = lane & 3;

    const size_t rowbase = (size_t)(b * la::SEQ + c * la::CHUNK) * 3072 + h * 64;
    const __half* kg = g_qkv + rowbase + 1024;
    const __half* vg = g_qkv + rowbase + 2048;

#pragma unroll
    for (int i = 0; i < 4; i++) {
        int idx = i * 256 + tid;
        int t = idx >> 3, d0 = (idx & 7) << 3;
        __half h8[8];
        *(uint4*)h8 = *(const uint4*)(kg + (size_t)t * 3072 + d0);
#pragma unroll
        for (int j = 0; j < 8; j++) sKT[(d0 + j) * 136 + t] = h8[j];
        *(uint4*)h8 = *(const uint4*)(vg + (size_t)t * 3072 + d0);
#pragma unroll
        for (int j = 0; j < 8; j++) sVT[(d0 + j) * 136 + t] = h8[j];
    }
    __syncthreads();

    const int wm = (wid & 3) * 16, wn = (wid >> 2) * 32;
    const uint32_t* uK = (const uint32_t*)sKT;   // stride 68 uints
    const uint32_t* uV = (const uint32_t*)sVT;
    float acc[4][4];
#pragma unroll
    for (int nt = 0; nt < 4; nt++)
#pragma unroll
        for (int i = 0; i < 4; i++) acc[nt][i] = 0.f;

#pragma unroll
    for (int ks = 0; ks < 8; ks++) {
        const int kb = ks * 8;
        uint32_t af[4];
        af[0] = uK[(wm + g) * 68 + kb + tig];
        af[1] = uK[(wm + g + 8) * 68 + kb + tig];
        af[2] = uK[(wm + g) * 68 + kb + tig + 4];
        af[3] = uK[(wm + g + 8) * 68 + kb + tig + 4];
#pragma unroll
        for (int nt = 0; nt < 4; nt++) {
            int n = wn + nt * 8 + g;
            uint32_t b0 = uV[n * 68 + kb + tig];
            uint32_t b1 = uV[n * 68 + kb + tig + 4];
            MMA_F16(acc[nt], af, b0, b1);
        }
    }
    float* outp = g_ckv + ((size_t)bh * la::NCHUNK + c) * 4096;
#pragma unroll
    for (int nt = 0; nt < 4; nt++) {
        int d = wm + g, m = wn + nt * 8 + tig * 2;
        *(float2*)(outp + d * 64 + m)       = make_float2(acc[nt][0], acc[nt][1]);
        *(float2*)(outp + (d + 8) * 64 + m) = make_float2(acc[nt][2], acc[nt][3]);
    }
    if (tid < 64) {
        const __half2* p = (const __half2*)(sKT + tid * 136);
        float s = 0.f;
#pragma unroll
        for (int t = 0; t < 64; t++) {
            float2 f = __half22float2(p[t]);
            s += f.x + f.y;
        }
        g_cks[((size_t)bh * la::NCHUNK + c) * 64 + tid] = s;
    }
}

// ---------------- exclusive prefix over chunks (fp32 state) ----------------
__global__ __launch_bounds__(256) void prefix_scan()
{
    const int bh  = blockIdx.x;
    const int seg = blockIdx.y;
    const int tid = threadIdx.x;

    float2* base = (float2*)(g_ckv + (size_t)bh * la::NCHUNK * 4096) + seg * 256 + tid;
    float2 vals[la::NCHUNK];
#pragma unroll
    for (int c = 0; c < la::NCHUNK; c++) vals[c] = base[c * 2048];
    float2 run = make_float2(0.f, 0.f);
#pragma unroll
    for (int c = 0; c < la::NCHUNK; c++) {
        float2 t = vals[c];
        vals[c] = run;
        run.x += t.x; run.y += t.y;
    }
#pragma unroll
    for (int c = 0; c < la::NCHUNK; c++) base[c * 2048] = vals[c];

    if (seg == 0 && tid < 64) {
        float* kb = g_cks + (size_t)bh * la::NCHUNK * 64 + tid;
        float kv[la::NCHUNK];
#pragma unroll
        for (int c = 0; c < la::NCHUNK; c++) kv[c] = kb[c * 64];
        float r = 0.f;
#pragma unroll
        for (int c = 0; c < la::NCHUNK; c++) { float t = kv[c]; kv[c] = r; r += t; }
#pragma unroll
        for (int c = 0; c < la::NCHUNK; c++) kb[c * 64] = kv[c];
    }
}

// ============ chunk_out: fp16 mma intra + inter ===========================
// smem halves: sQ[128][64]@0 str72 | sK[128][64]@9216 str72 (reused sVT[64][128] str136)
// sS[128][128]@18432 str136 | sKVT[64][64]@35840 str72 | fp32 sks/sden @45056h
static constexpr int CO_SMEM = 45056 * 2 + 192 * 4;   // 90880 B

__global__ __launch_bounds__(256) void chunk_out()
{
    extern __shared__ __half smh[];
    __half* sQ   = smh;            // [r][d] stride 72
    __half* sK   = smh + 9216;     // [t][d] stride 72 (later sVT stride 136)
    __half* sVT  = smh + 9216;     // [m][t]
    __half* sS   = smh + 18432;    // [r][j] stride 136
    __half* sKVT = smh + 35840;    // [m][d] stride 72
    float*  sks  = (float*)(smh + 45056);
    float*  sden = sks + 64;

    const int c  = blockIdx.x;
    const int bh = blockIdx.y;
    const int b  = bh >> 4, h = bh & 15;
    const int tid = threadIdx.x;
    const int wid = tid >> 5, lane = tid & 31;
    const int g = lane >> 2, tig = lane & 3;

    const size_t rowbase = (size_t)(b * la::SEQ + c * la::CHUNK) * 3072 + h * 64;
    const __half* qg = g_qkv + rowbase;
    const __half* kg = qg + 1024;
    const __half* vg = qg + 2048;

    // stage q,k row-major (contiguous copy)
#pragma unroll
    for (int i = 0; i < 4; i++) {
        int idx = i * 256 + tid;
        int t = idx >> 3, d0 = (idx & 7) << 3;
        *(uint4*)(sQ + t * 72 + d0) = *(const uint4*)(qg + (size_t)t * 3072 + d0);
        *(uint4*)(sK + t * 72 + d0) = *(const uint4*)(kg + (size_t)t * 3072 + d0);
    }
    const float* kvg = g_ckv + ((size_t)bh * la::NCHUNK + c) * 4096;
#pragma unroll
    for (int i = 0; i < 4; i++) {
        int idx = i * 256 + tid;
        int d = idx >> 4, m0 = (idx & 15) << 2;
        float4 kv4 = *(const float4*)(kvg + d * 64 + m0);
        sKVT[(m0 + 0) * 72 + d] = __float2half_rn(kv4.x);
        sKVT[(m0 + 1) * 72 + d] = __float2half_rn(kv4.y);
        sKVT[(m0 + 2) * 72 + d] = __float2half_rn(kv4.z);
        sKVT[(m0 + 3) * 72 + d] = __float2half_rn(kv4.w);
    }
    if (tid < 64) sks[tid] = g_cks[((size_t)bh * la::NCHUNK + c) * 64 + tid];
    __syncthreads();

    // stage1: S = Qf @ Kf^T (128x128x64, 4 k16 steps)
    {
        const int wm = (wid & 3) * 32, wn = (wid >> 2) * 64;
        const uint32_t* uA = (const uint32_t*)sQ;   // stride 36
        const uint32_t* uB = (const uint32_t*)sK;
        float acc[2][8][4];
#pragma unroll
        for (int mt = 0; mt < 2; mt++)
#pragma unroll
            for (int nt = 0; nt < 8; nt++)
#pragma unroll
                for (int i = 0; i < 4; i++) acc[mt][nt][i] = 0.f;
#pragma unroll
        for (int ks = 0; ks < 4; ks++) {
            const int kb = ks * 8;
            uint32_t af[2][4];
#pragma unroll
            for (int mt = 0; mt < 2; mt++) {
                int r = wm + mt * 16 + g;
                af[mt][0] = uA[r * 36 + kb + tig];
                af[mt][1] = uA[(r + 8) * 36 + kb + tig];
                af[mt][2] = uA[r * 36 + kb + tig + 4];
                af[mt][3] = uA[(r + 8) * 36 + kb + tig + 4];
            }
#pragma unroll
            for (int nt = 0; nt < 8; nt++) {
                int n = wn + nt * 8 + g;
                uint32_t b0 = uB[n * 36 + kb + tig];
                uint32_t b1 = uB[n * 36 + kb + tig + 4];
                MMA_F16(acc[0][nt], af[0], b0, b1);
                MMA_F16(acc[1][nt], af[1], b0, b1);
            }
        }
        __syncthreads();  // all warps done reading sK before V overwrites

        // masked S -> fp16 smem
#pragma unroll
        for (int mt = 0; mt < 2; mt++) {
            int r0 = wm + mt * 16 + g, r1 = r0 + 8;
#pragma unroll
            for (int nt = 0; nt < 8; nt++) {
                int j0 = wn + nt * 8 + tig * 2;
                float v00 = (j0     <= r0) ? acc[mt][nt][0] : 0.f;
                float v01 = (j0 + 1 <= r0) ? acc[mt][nt][1] : 0.f;
                float v10 = (j0     <= r1) ? acc[mt][nt][2] : 0.f;
                float v11 = (j0 + 1 <= r1) ? acc[mt][nt][3] : 0.f;
                *(__half2*)(sS + r0 * 136 + j0) = __floats2half2_rn(v00, v01);
                *(__half2*)(sS + r1 * 136 + j0) = __floats2half2_rn(v10, v11);
            }
        }
    }
    // stage V^T into old sK region
#pragma unroll
    for (int i = 0; i < 4; i++) {
        int idx = i * 256 + tid;
        int t = idx >> 3, m0 = (idx & 7) << 3;
        __half h8[8];
        *(uint4*)h8 = *(const uint4*)(vg + (size_t)t * 3072 + m0);
#pragma unroll
        for (int j = 0; j < 8; j++) sVT[(m0 + j) * 136 + t] = h8[j];
    }
    __syncthreads();

    // denom per row (fp32)
    if (tid < 128) {
        const int r = tid;
        float s = 0.f;
        const __half2* ps = (const __half2*)(sS + r * 136);
#pragma unroll
        for (int j = 0; j < 64; j++) {
            float2 f = __half22float2(ps[j]);
            s += f.x + f.y;
        }
        const __half2* pq = (const __half2*)(sQ + r * 72);
#pragma unroll
        for (int d = 0; d < 32; d++) {
            float2 fq = __half22float2(pq[d]);
            s = fmaf(fq.x, sks[2 * d], s);
            s = fmaf(fq.y, sks[2 * d + 1], s);
        }
        sden[r] = fmaxf(s, 1e-6f);
    }
    __syncthreads();

    // stage2: out = S_masked @ V (8 steps) + Qf @ KV^T (4 steps)
    {
        const int wm = (wid & 3) * 32, wn = (wid >> 2) * 32;
        const uint32_t* uS  = (const uint32_t*)sS;    // stride 68
        const uint32_t* uV  = (const uint32_t*)sVT;   // stride 68
        const uint32_t* uQ  = (const uint32_t*)sQ;    // stride 36
        const uint32_t* uKV = (const uint32_t*)sKVT;  // stride 36
        float acc[2][4][4];
#pragma unroll
        for (int mt = 0; mt < 2; mt++)
#pragma unroll
            for (int nt = 0; nt < 4; nt++)
#pragma unroll
                for (int i = 0; i < 4; i++) acc[mt][nt][i] = 0.f;

#pragma unroll
        for (int ks = 0; ks < 8; ks++) {
            const int kb = ks * 8;
            uint32_t af[2][4];
#pragma unroll
            for (int mt = 0; mt < 2; mt++) {
                int r = wm + mt * 16 + g;
                af[mt][0] = uS[r * 68 + kb + tig];
                af[mt][1] = uS[(r + 8) * 68 + kb + tig];
                af[mt][2] = uS[r * 68 + kb + tig + 4];
                af[mt][3] = uS[(r + 8) * 68 + kb + tig + 4];
            }
#pragma unroll
            for (int nt = 0; nt < 4; nt++) {
                int n = wn + nt * 8 + g;
                uint32_t b0 = uV[n * 68 + kb + tig];
                uint32_t b1 = uV[n * 68 + kb + tig + 4];
                MMA_F16(acc[0][nt], af[0], b0, b1);
                MMA_F16(acc[1][nt], af[1], b0, b1);
            }
        }
#pragma unroll
        for (int ks = 0; ks < 4; ks++) {
            const int kb = ks * 8;
            uint32_t af[2][4];
#pragma unroll
            for (int mt = 0; mt < 2; mt++) {
                int r = wm + mt * 16 + g;
                af[mt][0] = uQ[r * 36 + kb + tig];
                af[mt][1] = uQ[(r + 8) * 36 + kb + tig];
                af[mt][2] = uQ[r * 36 + kb + tig + 4];
                af[mt][3] = uQ[(r + 8) * 36 + kb + tig + 4];
            }
#pragma unroll
            for (int nt = 0; nt < 4; nt++) {
                int n = wn + nt * 8 + g;
                uint32_t b0 = uKV[n * 36 + kb + tig];
                uint32_t b1 = uKV[n * 36 + kb + tig + 4];
                MMA_F16(acc[0][nt], af[0], b0, b1);
                MMA_F16(acc[1][nt], af[1], b0, b1);
            }
        }

        // epilogue: divide, write fp16 attn
#pragma unroll
        for (int mt = 0; mt < 2; mt++) {
            int r0 = wm + mt * 16 + g, r1 = r0 + 8;
            float inv0 = 1.0f / sden[r0];
            float inv1 = 1.0f / sden[r1];
            __half* o0 = g_attn + (size_t)(b * la::SEQ + c * la::CHUNK + r0) * 1024 + h * 64;
            __half* o1 = g_attn + (size_t)(b * la::SEQ + c * la::CHUNK + r1) * 1024 + h * 64;
#pragma unroll
            for (int nt = 0; nt < 4; nt++) {
                int m = wn + nt * 8 + tig * 2;
                *(__half2*)(o0 + m) = __floats2half2_rn(acc[mt][nt][0] * inv0,
                                                        acc[mt][nt][1] * inv0);
                *(__half2*)(o1 + m) = __floats2half2_rn(acc[mt][nt][2] * inv1,
                                                        acc[mt][nt][3] * inv1);
            }
        }
    }
}

// ---------------- launch ----------------
extern "C" void kernel_launch(void* const* d_in, const int* in_sizes, int n_in,
                              void* d_out, int out_size)
{
    const float* x    = (const float*)d_in[0];
    const float* wqkv = (const float*)d_in[1];
    const float* wout = (const float*)d_in[2];
    float*       out  = (float*)d_out;

    __half *qkvh, *attn, *wTh, *xh;
    cudaGetSymbolAddress((void**)&qkvh, g_qkv);
    cudaGetSymbolAddress((void**)&attn, g_attn);
    cudaGetSymbolAddress((void**)&wTh, g_wTh);
    cudaGetSymbolAddress((void**)&xh, g_xh);
    __half* wqkvTh = wTh;
    __half* woutTh = wTh + 3072 * 1024;

    cudaFuncSetAttribute(gemm_h,     cudaFuncAttributeMaxDynamicSharedMemorySize, GH_SMEM);
    cudaFuncSetAttribute(chunk_sums, cudaFuncAttributeMaxDynamicSharedMemorySize, CS_SMEM);
    cudaFuncSetAttribute(chunk_out,  cudaFuncAttributeMaxDynamicSharedMemorySize, CO_SMEM);

    // 0) rope LUT, fp16 weight transposes, fp16 x
    rope_lut_build<<<la::SEQ, 32>>>();
    transpose_w_h<<<dim3(3072 / 32, 1024 / 32), 256>>>(wqkv, wqkvTh, 1024, 3072);
    transpose_w_h<<<dim3(1024 / 32, 1024 / 32), 256>>>(wout, woutTh, 1024, 1024);
    round_f16_k<<<la::ROWS * la::DIM / 2048, 256>>>(x, xh);

    // 1) qkv = x @ w_qkv (fp16 mma), rope+elu fused, fp16 out
    gemm_h<<<dim3(3072 / 128, la::ROWS / 128), 256, GH_SMEM>>>(xh, wqkvTh, nullptr, qkvh,
                                                               la::ROWS, 3072, 1024, 1);

    // 2) per-chunk KV sums (fp16 mma, fp32 out)
    dim3 g3(la::NCHUNK, la::NB * la::NHEADS);
    chunk_sums<<<g3, 256, CS_SMEM>>>();

    // 3) exclusive prefix over chunks (fp32)
    prefix_scan<<<dim3(la::NB * la::NHEADS, 8), 256>>>();

    // 4) per-chunk outputs (fp16 mma, fp16 attn out)
    chunk_out<<<g3, 256, CO_SMEM>>>();

    // 5) out = attn @ w_out (fp16 mma, fp32 out)
    gemm_h<<<dim3(1024 / 128, la::ROWS / 128), 256, GH_SMEM>>>(attn, woutTh, out, nullptr,
                                                               la::ROWS, 1024, 1024, 0);
}

// round 14
// speedup vs baseline: 2.7669x; 1.0413x over previous
#include <cuda_runtime.h>
#include <cuda_fp16.h>
#include <math.h>
#include <stdint.h>

// ---------------- problem constants ----------------
namespace la {
constexpr int DIM    = 1024;
constexpr int NHEADS = 16;
constexpr int HD     = 64;
constexpr int NB     = 4;
constexpr int SEQ    = 4096;
constexpr int ROWS   = NB * SEQ; // 16384
constexpr int CHUNK  = 128;
constexpr int NCHUNK = SEQ / CHUNK; // 32
}

// ---------------- scratch (device globals: allocation-free) ----------------
__device__ __half g_qkv[(size_t)la::ROWS * 3 * la::DIM];          // fp16 (q,k featurized)
__device__ __half g_attn[(size_t)la::ROWS * la::DIM];             // fp16
__device__ float  g_ckv[(size_t)la::NB * la::NHEADS * la::NCHUNK * la::HD * la::HD];
__device__ float  g_cks[(size_t)la::NB * la::NHEADS * la::NCHUNK * la::HD];
__device__ __half g_wTh[3072 * 1024 + 1024 * 1024];               // fp16 transposed weights
__device__ __half g_xh[(size_t)la::ROWS * la::DIM];               // fp16 x
__device__ float2 g_lut[la::SEQ * 32];

// ---------------- helpers ----------------
__device__ __forceinline__ uint32_t smem_u32(const void* p) {
    uint32_t a;
    asm("{ .reg .u64 t; cvta.to.shared.u64 t, %1; cvt.u32.u64 %0, t; }" : "=r"(a) : "l"(p));
    return a;
}

#define MMA_F16(c, a, b0, b1)                                               \
    asm volatile("mma.sync.aligned.m16n8k16.row.col.f32.f16.f16.f32 "       \
                 "{%0,%1,%2,%3},{%4,%5,%6,%7},{%8,%9},{%0,%1,%2,%3};"       \
                 : "+f"((c)[0]), "+f"((c)[1]), "+f"((c)[2]), "+f"((c)[3])   \
                 : "r"((a)[0]), "r"((a)[1]), "r"((a)[2]), "r"((a)[3]),      \
                   "r"(b0), "r"(b1))

#define CP_ASYNC16(dst, src) \
    asm volatile("cp.async.cg.shared.global [%0], [%1], 16;" :: "r"(dst), "l"(src) : "memory")
#define CP_COMMIT  asm volatile("cp.async.commit_group;" ::: "memory")
#define CP_WAIT1   asm volatile("cp.async.wait_group 1;" ::: "memory")

__device__ __forceinline__ float elu1(float z) {
    return (z > 0.f) ? (z + 1.0f) : expf(z);
}
constexpr float ROPE_SC = 0.35355339059327373f; // 64^(-1/4)

// ============ rope LUT build ==============================================
__global__ void rope_lut_build()
{
    const int n = blockIdx.x, lane = threadIdx.x;
    float pw   = powf(10000.0f, (float)lane * (1.0f / 32.0f));
    float invf = 1.0f / pw;
    float ang  = (float)n * invf;
    float s, c;
    sincosf(ang, &s, &c);
    g_lut[n * 32 + lane] = make_float2(c, s);
}

// ============ fp32 -> fp16 round pass =====================================
__global__ __launch_bounds__(256) void round_f16_k(const float* __restrict__ src,
                                                   __half* __restrict__ dst)
{
    const size_t i = ((size_t)blockIdx.x * 256 + threadIdx.x) * 8;
    float4 v1 = *(const float4*)(src + i);
    float4 v2 = *(const float4*)(src + i + 4);
    __half2 h[4] = { __floats2half2_rn(v1.x, v1.y), __floats2half2_rn(v1.z, v1.w),
                     __floats2half2_rn(v2.x, v2.y), __floats2half2_rn(v2.z, v2.w) };
    *(uint4*)(dst + i) = *(uint4*)h;
}

// ============ fp16 GEMM: C = A[M,K] @ Bt[N,K]^T ===========================
// 128x128 CTA tile, BK=32 (2 x k16 steps), 256 threads, 8 warps,
// warp tile 32x64, occ 2, cp.async 3-stage.
// mode 0: plain fp32 out to Cf (gemm2).
// mode 1: fused qkv. Tile 0-7 = q cols; tile 8-23 = (k-head h | v-head h)
//   paired. kv-CTAs featurize k, store k/v to g_qkv (standard layout), then
//   compute KV_c = K^T V and ks in-CTA (replaces chunk_sums kernel).
static constexpr int GH_STRU   = 20;
static constexpr int GH_ROWB   = 80;
static constexpr int GH_TILE_B = 128 * GH_ROWB;
static constexpr int GH_STAGE  = 2 * GH_TILE_B;
static constexpr int GH_SMEM   = 3 * GH_STAGE;       // 61440 B

__global__ __launch_bounds__(256, 2) void gemm_h(const __half* __restrict__ A,
                                                 const __half* __restrict__ Bt,
                                                 float* __restrict__ Cf,
                                                 __half* __restrict__ Ch,
                                                 int M, int N, int K, int mode)
{
    extern __shared__ char smc[];
    const uint32_t sbase = smem_u32(smc);

    const int tid  = threadIdx.x;
    const int wid  = tid >> 5, lane = tid & 31;
    const int g    = lane >> 2, tig = lane & 3;
    const int wm   = (wid & 3) * 32, wn = (wid >> 2) * 64;

    const int tile   = blockIdx.x;
    const bool kvCTA = (mode == 1) && (tile >= 8);
    const int hKV    = tile - 8;     // head for kv tiles

    const __half* Ab = A + (size_t)blockIdx.y * 128 * K;

    const int lr = tid >> 1, lqh = (tid & 1) * 16;
    // B row for this thread's loads (column permutation for kv tiles)
    int grow;
    if (kvCTA) grow = (lr < 64) ? (1024 + hKV * 64 + lr) : (2048 + hKV * 64 + lr - 64);
    else       grow = tile * 128 + lr;
    const __half* Bb = Bt + (size_t)grow * K;

    auto load_stage = [&](int s, int kc) {
        const uint32_t base = sbase + s * GH_STAGE;
        const uint32_t off  = lr * GH_ROWB + lqh * 2;
        const __half* sa = Ab + (size_t)lr * K + kc * 32 + lqh;
        const __half* sb = Bb + kc * 32 + lqh;
        CP_ASYNC16(base + off,                  sa);
        CP_ASYNC16(base + off + 16,             sa + 8);
        CP_ASYNC16(base + GH_TILE_B + off,      sb);
        CP_ASYNC16(base + GH_TILE_B + off + 16, sb + 8);
        CP_COMMIT;
    };

    float acc[2][8][4];
#pragma unroll
    for (int mt = 0; mt < 2; mt++)
#pragma unroll
        for (int nt = 0; nt < 8; nt++)
#pragma unroll
            for (int i = 0; i < 4; i++) acc[mt][nt][i] = 0.f;

    auto compute = [&](int buf) {
        const uint32_t* uA = (const uint32_t*)(smc + buf * GH_STAGE);
        const uint32_t* uB = uA + 128 * GH_STRU;
#pragma unroll
        for (int ks = 0; ks < 2; ks++) {
            const int kb = ks * 8;
            uint32_t af[2][4];
#pragma unroll
            for (int mt = 0; mt < 2; mt++) {
                int r = wm + mt * 16 + g;
                af[mt][0] = uA[r * GH_STRU + kb + tig];
                af[mt][1] = uA[(r + 8) * GH_STRU + kb + tig];
                af[mt][2] = uA[r * GH_STRU + kb + tig + 4];
                af[mt][3] = uA[(r + 8) * GH_STRU + kb + tig + 4];
            }
#pragma unroll
            for (int nt = 0; nt < 8; nt++) {
                int n = wn + nt * 8 + g;
                uint32_t b0 = uB[n * GH_STRU + kb + tig];
                uint32_t b1 = uB[n * GH_STRU + kb + tig + 4];
                MMA_F16(acc[0][nt], af[0], b0, b1);
                MMA_F16(acc[1][nt], af[1], b0, b1);
            }
        }
    };

    load_stage(0, 0);
    load_stage(1, 1);

    const int KC = K >> 5;
    for (int kc = 0; kc < KC; kc++) {
        CP_WAIT1;
        __syncthreads();
        compute(kc % 3);
        if (kc + 2 < KC) load_stage((kc + 2) % 3, kc + 2);
        else             CP_COMMIT;
    }

    // ---------------- epilogue ----------------
    if (mode == 0) {
#pragma unroll
        for (int mt = 0; mt < 2; mt++) {
            const int row0 = blockIdx.y * 128 + wm + mt * 16 + g;
#pragma unroll
            for (int nt = 0; nt < 8; nt++) {
                const int col = tile * 128 + wn + nt * 8 + tig * 2;
                *(float2*)(Cf + (size_t)row0 * N + col) =
                    make_float2(acc[mt][nt][0], acc[mt][nt][1]);
                *(float2*)(Cf + (size_t)(row0 + 8) * N + col) =
                    make_float2(acc[mt][nt][2], acc[mt][nt][3]);
            }
        }
        return;
    }

    if (!kvCTA) {
        // q tile: rope+elu+scale, fp16 store. pair (d, d+32) thread-local.
        const int colbase = tile * 128 + wn;   // head-aligned (64)
#pragma unroll
        for (int mt = 0; mt < 2; mt++) {
            const int r0 = blockIdx.y * 128 + wm + mt * 16 + g;
#pragma unroll
            for (int half = 0; half < 2; half++) {
                const int row = r0 + half * 8;
                const int n4  = row & (la::SEQ - 1);
#pragma unroll
                for (int nt = 0; nt < 4; nt++) {
#pragma unroll
                    for (int e = 0; e < 2; e++) {
                        const int d  = nt * 8 + tig * 2 + e;
                        const int ai = half * 2 + e;
                        float x1 = acc[mt][nt][ai];
                        float x2 = acc[mt][nt + 4][ai];
                        float2 cs = g_lut[n4 * 32 + d];
                        float o1 = (x1 * cs.x - x2 * cs.y) * ROPE_SC;
                        float o2 = (x1 * cs.y + x2 * cs.x) * ROPE_SC;
                        Ch[(size_t)row * 3072 + colbase + d]      = __float2half_rn(elu1(o1));
                        Ch[(size_t)row * 3072 + colbase + d + 32] = __float2half_rn(elu1(o2));
                    }
                }
            }
        }
        return;
    }

    // ---- kv tile: featurize k, store k/v, then in-CTA KV = K^T V + ks ----
    __syncthreads();   // all warps done with pipeline smem before reuse
    __half* sKT = (__half*)smc;          // [d=64][t=128] stride 136
    __half* sVT = sKT + 64 * 136;        // [m=64][t=128] stride 136

    if (wn == 0) {
        // k half (warps 0-3): featurize + store to g_qkv and sKT (transposed)
#pragma unroll
        for (int mt = 0; mt < 2; mt++) {
            const int t0 = wm + mt * 16 + g;
#pragma unroll
            for (int half = 0; half < 2; half++) {
                const int t   = t0 + half * 8;
                const int row = blockIdx.y * 128 + t;
                const int n4  = row & (la::SEQ - 1);
#pragma unroll
                for (int nt = 0; nt < 4; nt++) {
#pragma unroll
                    for (int e = 0; e < 2; e++) {
                        const int d  = nt * 8 + tig * 2 + e;
                        const int ai = half * 2 + e;
                        float x1 = acc[mt][nt][ai];
                        float x2 = acc[mt][nt + 4][ai];
                        float2 cs = g_lut[n4 * 32 + d];
                        float o1 = (x1 * cs.x - x2 * cs.y) * ROPE_SC;
                        float o2 = (x1 * cs.y + x2 * cs.x) * ROPE_SC;
                        __half h1 = __float2half_rn(elu1(o1));
                        __half h2 = __float2half_rn(elu1(o2));
                        Ch[(size_t)row * 3072 + 1024 + hKV * 64 + d]      = h1;
                        Ch[(size_t)row * 3072 + 1024 + hKV * 64 + d + 32] = h2;
                        sKT[d * 136 + t]        = h1;
                        sKT[(d + 32) * 136 + t] = h2;
                    }
                }
            }
        }
    } else {
        // v half (warps 4-7): plain store to g_qkv and sVT (transposed)
#pragma unroll
        for (int mt = 0; mt < 2; mt++) {
            const int t0 = wm + mt * 16 + g;
#pragma unroll
            for (int half = 0; half < 2; half++) {
                const int t   = t0 + half * 8;
                const int row = blockIdx.y * 128 + t;
#pragma unroll
                for (int nt = 0; nt < 8; nt++) {
                    const int m  = nt * 8 + tig * 2;
                    const int ai = half * 2;
                    __half h1 = __float2half_rn(acc[mt][nt][ai]);
                    __half h2 = __float2half_rn(acc[mt][nt][ai + 1]);
                    *(__half2*)(Ch + (size_t)row * 3072 + 2048 + hKV * 64 + m) =
                        __halves2half2(h1, h2);
                    sVT[m * 136 + t]       = h1;
                    sVT[(m + 1) * 136 + t] = h2;
                }
            }
        }
    }
    __syncthreads();

    // KV[d][m] = sum_t K[t][d] V[t][m]; warp tile 16x32, 8 k16 steps
    {
        const int b  = blockIdx.y >> 5;
        const int c  = blockIdx.y & 31;
        const int bh = b * 16 + hKV;
        const int wm2 = (wid & 3) * 16, wn2 = (wid >> 2) * 32;
        const uint32_t* uK = (const uint32_t*)sKT;   // stride 68 uints
        const uint32_t* uV = (const uint32_t*)sVT;
        float kacc[4][4];
#pragma unroll
        for (int nt = 0; nt < 4; nt++)
#pragma unroll
            for (int i = 0; i < 4; i++) kacc[nt][i] = 0.f;

#pragma unroll
        for (int ks = 0; ks < 8; ks++) {
            const int kb = ks * 8;
            uint32_t af[4];
            af[0] = uK[(wm2 + g) * 68 + kb + tig];
            af[1] = uK[(wm2 + g + 8) * 68 + kb + tig];
            af[2] = uK[(wm2 + g) * 68 + kb + tig + 4];
            af[3] = uK[(wm2 + g + 8) * 68 + kb + tig + 4];
#pragma unroll
            for (int nt = 0; nt < 4; nt++) {
                int n = wn2 + nt * 8 + g;
                uint32_t b0 = uV[n * 68 + kb + tig];
                uint32_t b1 = uV[n * 68 + kb + tig + 4];
                MMA_F16(kacc[nt], af, b0, b1);
            }
        }
        float* outp = g_ckv + ((size_t)bh * la::NCHUNK + c) * 4096;
#pragma unroll
        for (int nt = 0; nt < 4; nt++) {
            int d = wm2 + g, m = wn2 + nt * 8 + tig * 2;
            *(float2*)(outp + d * 64 + m)       = make_float2(kacc[nt][0], kacc[nt][1]);
            *(float2*)(outp + (d + 8) * 64 + m) = make_float2(kacc[nt][2], kacc[nt][3]);
        }
        if (tid < 64) {
            const __half2* p = (const __half2*)(sKT + tid * 136);
            float s = 0.f;
#pragma unroll
            for (int t = 0; t < 64; t++) {
                float2 f = __half22float2(p[t]);
                s += f.x + f.y;
            }
            g_cks[((size_t)bh * la::NCHUNK + c) * 64 + tid] = s;
        }
    }
}

// ---------------- weight transpose -> fp16 ---------------------------------
__global__ __launch_bounds__(256) void transpose_w_h(const float* __restrict__ src,
                                                     __half* __restrict__ dst,
                                                     int R, int Ccols)
{
    __shared__ float t[32][33];
    const int bx = blockIdx.x * 32, by = blockIdx.y * 32;
    const int x = threadIdx.x & 31, y = threadIdx.x >> 5;
#pragma unroll
    for (int i = 0; i < 32; i += 8)
        t[y + i][x] = src[(size_t)(by + y + i) * Ccols + bx + x];
    __syncthreads();
#pragma unroll
    for (int i = 0; i < 32; i += 8)
        dst[(size_t)(bx + y + i) * R + by + x] = __float2half_rn(t[x][y + i]);
}

// ---------------- exclusive prefix over chunks (fp32 state) ----------------
__global__ __launch_bounds__(256) void prefix_scan()
{
    const int bh  = blockIdx.x;
    const int seg = blockIdx.y;
    const int tid = threadIdx.x;

    float2* base = (float2*)(g_ckv + (size_t)bh * la::NCHUNK * 4096) + seg * 256 + tid;
    float2 vals[la::NCHUNK];
#pragma unroll
    for (int c = 0; c < la::NCHUNK; c++) vals[c] = base[c * 2048];
    float2 run = make_float2(0.f, 0.f);
#pragma unroll
    for (int c = 0; c < la::NCHUNK; c++) {
        float2 t = vals[c];
        vals[c] = run;
        run.x += t.x; run.y += t.y;
    }
#pragma unroll
    for (int c = 0; c < la::NCHUNK; c++) base[c * 2048] = vals[c];

    if (seg == 0 && tid < 64) {
        float* kb = g_cks + (size_t)bh * la::NCHUNK * 64 + tid;
        float kv[la::NCHUNK];
#pragma unroll
        for (int c = 0; c < la::NCHUNK; c++) kv[c] = kb[c * 64];
        float r = 0.f;
#pragma unroll
        for (int c = 0; c < la::NCHUNK; c++) { float t = kv[c]; kv[c] = r; r += t; }
#pragma unroll
        for (int c = 0; c < la::NCHUNK; c++) kb[c * 64] = kv[c];
    }
}

// ============ chunk_out: fp16 mma intra + inter ===========================
static constexpr int CO_SMEM = 45056 * 2 + 192 * 4;   // 90880 B

__global__ __launch_bounds__(256) void chunk_out()
{
    extern __shared__ __half smh[];
    __half* sQ   = smh;            // [r][d] stride 72
    __half* sK   = smh + 9216;     // [t][d] stride 72 (later sVT stride 136)
    __half* sVT  = smh + 9216;     // [m][t]
    __half* sS   = smh + 18432;    // [r][j] stride 136
    __half* sKVT = smh + 35840;    // [m][d] stride 72
    float*  sks  = (float*)(smh + 45056);
    float*  sden = sks + 64;

    const int c  = blockIdx.x;
    const int bh = blockIdx.y;
    const int b  = bh >> 4, h = bh & 15;
    const int tid = threadIdx.x;
    const int wid = tid >> 5, lane = tid & 31;
    const int g = lane >> 2, tig = lane & 3;

    const size_t rowbase = (size_t)(b * la::SEQ + c * la::CHUNK) * 3072 + h * 64;
    const __half* qg = g_qkv + rowbase;
    const __half* kg = qg + 1024;
    const __half* vg = qg + 2048;

    // stage q,k row-major (contiguous copy)
#pragma unroll
    for (int i = 0; i < 4; i++) {
        int idx = i * 256 + tid;
        int t = idx >> 3, d0 = (idx & 7) << 3;
        *(uint4*)(sQ + t * 72 + d0) = *(const uint4*)(qg + (size_t)t * 3072 + d0);
        *(uint4*)(sK + t * 72 + d0) = *(const uint4*)(kg + (size_t)t * 3072 + d0);
    }
    const float* kvg = g_ckv + ((size_t)bh * la::NCHUNK + c) * 4096;
#pragma unroll
    for (int i = 0; i < 4; i++) {
        int idx = i * 256 + tid;
        int d = idx >> 4, m0 = (idx & 15) << 2;
        float4 kv4 = *(const float4*)(kvg + d * 64 + m0);
        sKVT[(m0 + 0) * 72 + d] = __float2half_rn(kv4.x);
        sKVT[(m0 + 1) * 72 + d] = __float2half_rn(kv4.y);
        sKVT[(m0 + 2) * 72 + d] = __float2half_rn(kv4.z);
        sKVT[(m0 + 3) * 72 + d] = __float2half_rn(kv4.w);
    }
    if (tid < 64) sks[tid] = g_cks[((size_t)bh * la::NCHUNK + c) * 64 + tid];
    __syncthreads();

    // stage1: S = Qf @ Kf^T (128x128x64, 4 k16 steps)
    {
        const int wm = (wid & 3) * 32, wn = (wid >> 2) * 64;
        const uint32_t* uA = (const uint32_t*)sQ;   // stride 36
        const uint32_t* uB = (const uint32_t*)sK;
        float acc[2][8][4];
#pragma unroll
        for (int mt = 0; mt < 2; mt++)
#pragma unroll
            for (int nt = 0; nt < 8; nt++)
#pragma unroll
                for (int i = 0; i < 4; i++) acc[mt][nt][i] = 0.f;
#pragma unroll
        for (int ks = 0; ks < 4; ks++) {
            const int kb = ks * 8;
            uint32_t af[2][4];
#pragma unroll
            for (int mt = 0; mt < 2; mt++) {
                int r = wm + mt * 16 + g;
                af[mt][0] = uA[r * 36 + kb + tig];
                af[mt][1] = uA[(r + 8) * 36 + kb + tig];
                af[mt][2] = uA[r * 36 + kb + tig + 4];
                af[mt][3] = uA[(r + 8) * 36 + kb + tig + 4];
            }
#pragma unroll
            for (int nt = 0; nt < 8; nt++) {
                int n = wn + nt * 8 + g;
                uint32_t b0 = uB[n * 36 + kb + tig];
                uint32_t b1 = uB[n * 36 + kb + tig + 4];
                MMA_F16(acc[0][nt], af[0], b0, b1);
                MMA_F16(acc[1][nt], af[1], b0, b1);
            }
        }
        __syncthreads();  // all warps done reading sK before V overwrites

        // masked S -> fp16 smem
#pragma unroll
        for (int mt = 0; mt < 2; mt++) {
            int r0 = wm + mt * 16 + g, r1 = r0 + 8;
#pragma unroll
            for (int nt = 0; nt < 8; nt++) {
                int j0 = wn + nt * 8 + tig * 2;
                float v00 = (j0     <= r0) ? acc[mt][nt][0] : 0.f;
                float v01 = (j0 + 1 <= r0) ? acc[mt][nt][1] : 0.f;
                float v10 = (j0     <= r1) ? acc[mt][nt][2] : 0.f;
                float v11 = (j0 + 1 <= r1) ? acc[mt][nt][3] : 0.f;
                *(__half2*)(sS + r0 * 136 + j0) = __floats2half2_rn(v00, v01);
                *(__half2*)(sS + r1 * 136 + j0) = __floats2half2_rn(v10, v11);
            }
        }
    }
    // stage V^T into old sK region
#pragma unroll
    for (int i = 0; i < 4; i++) {
        int idx = i * 256 + tid;
        int t = idx >> 3, m0 = (idx & 7) << 3;
        __half h8[8];
        *(uint4*)h8 = *(const uint4*)(vg + (size_t)t * 3072 + m0);
#pragma unroll
        for (int j = 0; j < 8; j++) sVT[(m0 + j) * 136 + t] = h8[j];
    }
    __syncthreads();

    // denom per row (fp32)
    if (tid < 128) {
        const int r = tid;
        float s = 0.f;
        const __half2* ps = (const __half2*)(sS + r * 136);
#pragma unroll
        for (int j = 0; j < 64; j++) {
            float2 f = __half22float2(ps[j]);
            s += f.x + f.y;
        }
        const __half2* pq = (const __half2*)(sQ + r * 72);
#pragma unroll
        for (int d = 0; d < 32; d++) {
            float2 fq = __half22float2(pq[d]);
            s = fmaf(fq.x, sks[2 * d], s);
            s = fmaf(fq.y, sks[2 * d + 1], s);
        }
        sden[r] = fmaxf(s, 1e-6f);
    }
    __syncthreads();

    // stage2: out = S_masked @ V (8 steps) + Qf @ KV^T (4 steps)
    {
        const int wm = (wid & 3) * 32, wn = (wid >> 2) * 32;
        const uint32_t* uS  = (const uint32_t*)sS;    // stride 68
        const uint32_t* uV  = (const uint32_t*)sVT;   // stride 68
        const uint32_t* uQ  = (const uint32_t*)sQ;    // stride 36
        const uint32_t* uKV = (const uint32_t*)sKVT;  // stride 36
        float acc[2][4][4];
#pragma unroll
        for (int mt = 0; mt < 2; mt++)
#pragma unroll
            for (int nt = 0; nt < 4; nt++)
#pragma unroll
                for (int i = 0; i < 4; i++) acc[mt][nt][i] = 0.f;

#pragma unroll
        for (int ks = 0; ks < 8; ks++) {
            const int kb = ks * 8;
            uint32_t af[2][4];
#pragma unroll
            for (int mt = 0; mt < 2; mt++) {
                int r = wm + mt * 16 + g;
                af[mt][0] = uS[r * 68 + kb + tig];
                af[mt][1] = uS[(r + 8) * 68 + kb + tig];
                af[mt][2] = uS[r * 68 + kb + tig + 4];
                af[mt][3] = uS[(r + 8) * 68 + kb + tig + 4];
            }
#pragma unroll
            for (int nt = 0; nt < 4; nt++) {
                int n = wn + nt * 8 + g;
                uint32_t b0 = uV[n * 68 + kb + tig];
                uint32_t b1 = uV[n * 68 + kb + tig + 4];
                MMA_F16(acc[0][nt], af[0], b0, b1);
                MMA_F16(acc[1][nt], af[1], b0, b1);
            }
        }
#pragma unroll
        for (int ks = 0; ks < 4; ks++) {
            const int kb = ks * 8;
            uint32_t af[2][4];
#pragma unroll
            for (int mt = 0; mt < 2; mt++) {
                int r = wm + mt * 16 + g;
                af[mt][0] = uQ[r * 36 + kb + tig];
                af[mt][1] = uQ[(r + 8) * 36 + kb + tig];
                af[mt][2] = uQ[r * 36 + kb + tig + 4];
                af[mt][3] = uQ[(r + 8) * 36 + kb + tig + 4];
            }
#pragma unroll
            for (int nt = 0; nt < 4; nt++) {
                int n = wn + nt * 8 + g;
                uint32_t b0 = uKV[n * 36 + kb + tig];
                uint32_t b1 = uKV[n * 36 + kb + tig + 4];
                MMA_F16(acc[0][nt], af[0], b0, b1);
                MMA_F16(acc[1][nt], af[1], b0, b1);
            }
        }

        // epilogue: divide, write fp16 attn
#pragma unroll
        for (int mt = 0; mt < 2; mt++) {
            int r0 = wm + mt * 16 + g, r1 = r0 + 8;
            float inv0 = 1.0f / sden[r0];
            float inv1 = 1.0f / sden[r1];
            __half* o0 = g_attn + (size_t)(b * la::SEQ + c * la::CHUNK + r0) * 1024 + h * 64;
            __half* o1 = g_attn + (size_t)(b * la::SEQ + c * la::CHUNK + r1) * 1024 + h * 64;
#pragma unroll
            for (int nt = 0; nt < 4; nt++) {
                int m = wn + nt * 8 + tig * 2;
                *(__half2*)(o0 + m) = __floats2half2_rn(acc[mt][nt][0] * inv0,
                                                        acc[mt][nt][1] * inv0);
                *(__half2*)(o1 + m) = __floats2half2_rn(acc[mt][nt][2] * inv1,
                                                        acc[mt][nt][3] * inv1);
            }
        }
    }
}

// ---------------- launch ----------------
extern "C" void kernel_launch(void* const* d_in, const int* in_sizes, int n_in,
                              void* d_out, int out_size)
{
    const float* x    = (const float*)d_in[0];
    const float* wqkv = (const float*)d_in[1];
    const float* wout = (const float*)d_in[2];
    float*       out  = (float*)d_out;

    __half *qkvh, *attn, *wTh, *xh;
    cudaGetSymbolAddress((void**)&qkvh, g_qkv);
    cudaGetSymbolAddress((void**)&attn, g_attn);
    cudaGetSymbolAddress((void**)&wTh, g_wTh);
    cudaGetSymbolAddress((void**)&xh, g_xh);
    __half* wqkvTh = wTh;
    __half* woutTh = wTh + 3072 * 1024;

    cudaFuncSetAttribute(gemm_h,    cudaFuncAttributeMaxDynamicSharedMemorySize, GH_SMEM);
    cudaFuncSetAttribute(chunk_out, cudaFuncAttributeMaxDynamicSharedMemorySize, CO_SMEM);

    // 0) rope LUT, fp16 weight transposes, fp16 x
    rope_lut_build<<<la::SEQ, 32>>>();
    transpose_w_h<<<dim3(3072 / 32, 1024 / 32), 256>>>(wqkv, wqkvTh, 1024, 3072);
    transpose_w_h<<<dim3(1024 / 32, 1024 / 32), 256>>>(wout, woutTh, 1024, 1024);
    round_f16_k<<<la::ROWS * la::DIM / 2048, 256>>>(x, xh);

    // 1) qkv = x @ w_qkv (fp16 mma) with fused rope+elu AND per-chunk KV sums
    gemm_h<<<dim3(24, la::ROWS / 128), 256, GH_SMEM>>>(xh, wqkvTh, nullptr, qkvh,
                                                       la::ROWS, 3072, 1024, 1);

    // 2) exclusive prefix over chunks (fp32)
    prefix_scan<<<dim3(la::NB * la::NHEADS, 8), 256>>>();

    // 3) per-chunk outputs (fp16 mma, fp16 attn out)
    chunk_out<<<dim3(la::NCHUNK, la::NB * la::NHEADS), 256, CO_SMEM>>>();

    // 4) out = attn @ w_out (fp16 mma, fp32 out)
    gemm_h<<<dim3(1024 / 128, la::ROWS / 128), 256, GH_SMEM>>>(attn, woutTh, out, nullptr,
                                                               la::ROWS, 1024, 1024, 0);
}